// round 8
// baseline (speedup 1.0000x reference)
#include <cuda_runtime.h>

#define B 512
#define N 256
#define E_PER 8192
#define NT (B*N)
#define ET (B*E_PER)
#define FIN 128
#define H 32
#define K 16
#define FOUT 10
#define EPSF 1e-15f
#define FULL 0xffffffffu
#define WSTR 36         // padded transposed-weight stride
#define RS   260        // xs transpose stride

// ---------------- globals ----------------
__device__ float g_acc[2] = {0.f, 0.f};
__device__ int   g_ctr = 0;

// ---------------- f32x2 helpers ----------------
__device__ __forceinline__ unsigned long long pk2(float lo, float hi) {
    unsigned long long r;
    asm("mov.b64 %0, {%1,%2};" : "=l"(r)
        : "r"(__float_as_uint(lo)), "r"(__float_as_uint(hi)));
    return r;
}
__device__ __forceinline__ void fma2(unsigned long long& d,
                                     unsigned long long a, unsigned long long b) {
    asm("fma.rn.f32x2 %0, %1, %2, %0;" : "+l"(d) : "l"(a), "l"(b));
}
__device__ __forceinline__ void upk2(float& lo, float& hi, unsigned long long v) {
    unsigned int a, b2;
    asm("mov.b64 {%0,%1}, %2;" : "=r"(a), "=r"(b2) : "l"(v));
    lo = __uint_as_float(a); hi = __uint_as_float(b2);
}

// ---------------- mega-kernel shared layout ----------------
struct SMem {
    float h1[N*H];            // 32768 B
    float s[N*K];             // 16384 B (overlaid by ws[FIN*H] during lin1)
    float buf[2048];          // 8192  B
    float wr[H*WSTR];
    float wo[H*WSTR];
    float wp[K*WSTR];
    float aggb[8*32];
    float hcb[8*32];
    float br[H];
    float bp[K];
    float px[K*H];
    float adj[K*K];
    float ssm[K*K];
    float red[32];
    float tbuf[8*16];
    float sd[K];
    float sr[H];
    float sh3[H];
    float so[FOUT];
    alignas(16) unsigned short idx[E_PER];  // overlaid by xs[16*RS] during lin1
    int deg[N];               // xs overlay spills 256B into deg (rewritten later)
    int start[N];
    int cnt[N];
};

// ---------------- mega: entire network, one CTA per graph ----------------
__global__ __launch_bounds__(256, 2)
void k_mega(const float* __restrict__ x,
            const int* __restrict__ ei,
            const float* __restrict__ Wlin1, const float* __restrict__ blin1,
            const float* __restrict__ Wrel,  const float* __restrict__ brel,
            const float* __restrict__ Wroot, const float* __restrict__ Wpool,
            const float* __restrict__ bpool,
            const float* __restrict__ Wrel2, const float* __restrict__ brel2,
            const float* __restrict__ Wroot2,
            const float* __restrict__ Wlin2, const float* __restrict__ blin2,
            const float* __restrict__ Wlin3, const float* __restrict__ blin3,
            float* __restrict__ out, int out_size)
{
    extern __shared__ char smraw[];
    SMem* sm = (SMem*)smraw;
    int b = blockIdx.x, tid = threadIdx.x;
    int w = tid >> 5, lane = tid & 31;
    int base = b * N;

    // ---- prefetch edges into registers (latency hides under lin1) ----
    const int* srcg = ei + b*E_PER;
    const int* dstg = ei + ET + b*E_PER;
    int sv[E_PER/256], dvv[E_PER/256];
#pragma unroll
    for (int i = 0; i < E_PER/256; i++) {
        sv[i]  = srcg[tid + i*256] - base;
        dvv[i] = dstg[tid + i*256] - base;
    }

    // ---- stage conv/pool weights early (distinct smem regions) ----
    for (int i = tid; i < H*H; i += 256) {
        int k = i >> 5, l = i & 31;
        sm->wr[l*WSTR + k] = Wrel[i];
        sm->wo[l*WSTR + k] = Wroot[i];
    }
    for (int i = tid; i < H*K; i += 256) {
        int k = i >> 4, l = i & 15;
        sm->wp[l*WSTR + k] = Wpool[i];
    }
    if (tid < H) sm->br[tid] = brel[tid];
    if (tid < K) sm->bp[tid] = bpool[tid];
    sm->cnt[tid] = 0;

    // ================= fused lin1: h1 = x[b] @ W1 + b1 (FFMA2 tile) ==========
    {
        float* ws = sm->s;                 // overlay (s dead until phase A)
        float* xs = (float*)sm->idx;       // overlay (idx dead until sort)
        for (int i = tid; i < FIN*H; i += 256) ws[i] = Wlin1[i];

        int c0 = (tid & 7) * 4;
        int r0 = (tid >> 3) * 8;
        int lr = tid >> 2;
        int q  = tid & 3;

        float bsv[4];
#pragma unroll
        for (int c = 0; c < 4; c++) bsv[c] = blin1[c0 + c];

        const float* xg = x + (size_t)base * FIN;
        float4 nx[4];
#pragma unroll
        for (int p = 0; p < 4; p++)
            nx[p] = *(const float4*)&xg[(size_t)(lr + p*64)*FIN + q*4];

        unsigned long long acc[4][4];
#pragma unroll
        for (int pr = 0; pr < 4; pr++)
#pragma unroll
            for (int c = 0; c < 4; c++)
                acc[pr][c] = pk2(bsv[c], bsv[c]);

        for (int kt = 0; kt < 8; kt++) {
            __syncthreads();
#pragma unroll
            for (int p = 0; p < 4; p++) {
                int row = lr + p*64;
                xs[(q*4+0)*RS + row] = nx[p].x;
                xs[(q*4+1)*RS + row] = nx[p].y;
                xs[(q*4+2)*RS + row] = nx[p].z;
                xs[(q*4+3)*RS + row] = nx[p].w;
            }
            __syncthreads();
            if (kt < 7) {
#pragma unroll
                for (int p = 0; p < 4; p++)
                    nx[p] = *(const float4*)&xg[(size_t)(lr + p*64)*FIN + (kt+1)*16 + q*4];
            }
#pragma unroll
            for (int k = 0; k < 16; k++) {
                float4 wv = *(const float4*)&ws[(kt*16 + k)*H + c0];
                float4 xa = *(const float4*)&xs[k*RS + r0];
                float4 xb = *(const float4*)&xs[k*RS + r0 + 4];
                unsigned long long xp[4], wp2[4];
                xp[0] = pk2(xa.x, xa.y); xp[1] = pk2(xa.z, xa.w);
                xp[2] = pk2(xb.x, xb.y); xp[3] = pk2(xb.z, xb.w);
                wp2[0] = pk2(wv.x, wv.x); wp2[1] = pk2(wv.y, wv.y);
                wp2[2] = pk2(wv.z, wv.z); wp2[3] = pk2(wv.w, wv.w);
#pragma unroll
                for (int pr = 0; pr < 4; pr++) {
                    fma2(acc[pr][0], xp[pr], wp2[0]);
                    fma2(acc[pr][1], xp[pr], wp2[1]);
                    fma2(acc[pr][2], xp[pr], wp2[2]);
                    fma2(acc[pr][3], xp[pr], wp2[3]);
                }
            }
        }
#pragma unroll
        for (int pr = 0; pr < 4; pr++) {
            float lo[4], hi[4];
#pragma unroll
            for (int c = 0; c < 4; c++) upk2(lo[c], hi[c], acc[pr][c]);
            int gr = r0 + 2*pr;
            *(float4*)&sm->h1[gr*H + c0]     = make_float4(lo[0], lo[1], lo[2], lo[3]);
            *(float4*)&sm->h1[(gr+1)*H + c0] = make_float4(hi[0], hi[1], hi[2], hi[3]);
        }
    }
    __syncthreads();

    // ---- sort edges by src (from prefetched registers) ----
#pragma unroll
    for (int i = 0; i < E_PER/256; i++)
        atomicAdd(&sm->cnt[sv[i]], 1);
    __syncthreads();
    int d0 = sm->cnt[tid];
    sm->start[tid] = d0;
    __syncthreads();
    for (int off = 1; off < N; off <<= 1) {
        int v = (tid >= off) ? sm->start[tid - off] : 0;
        __syncthreads();
        sm->start[tid] += v;
        __syncthreads();
    }
    int st0 = sm->start[tid] - d0;
    sm->deg[tid] = d0;
    sm->start[tid] = st0;
    sm->cnt[tid] = st0;
    __syncthreads();
#pragma unroll
    for (int i = 0; i < E_PER/256; i++) {
        int p = atomicAdd(&sm->cnt[sv[i]], 1);
        sm->idx[p] = (unsigned short)dvv[i];
    }
    __syncthreads();

    // ---- Phase A: gather agg (MLP=2), conv1, pool, softmax, px rank-1 ----
    float px_reg[16];
#pragma unroll
    for (int k = 0; k < 16; k++) px_reg[k] = 0.f;

    {
        int grp = lane >> 3, q8 = lane & 7;
        const float4* h1r = (const float4*)sm->h1;
        for (int u = w*32; u < w*32 + 32; u++) {
            int d  = sm->deg[u];
            int st = sm->start[u];
            float4 a0 = make_float4(0.f, 0.f, 0.f, 0.f);
            float4 a1 = make_float4(0.f, 0.f, 0.f, 0.f);
            int i = grp;
            for (; i + 4 < d; i += 8) {
                int v0 = sm->idx[st + i];
                int v1 = sm->idx[st + i + 4];
                float4 r0 = h1r[v0*8 + q8];
                float4 r1 = h1r[v1*8 + q8];
                a0.x += r0.x; a0.y += r0.y; a0.z += r0.z; a0.w += r0.w;
                a1.x += r1.x; a1.y += r1.y; a1.z += r1.z; a1.w += r1.w;
            }
            if (i < d) {
                int v0 = sm->idx[st + i];
                float4 r0 = h1r[v0*8 + q8];
                a0.x += r0.x; a0.y += r0.y; a0.z += r0.z; a0.w += r0.w;
            }
            float4 a = make_float4(a0.x + a1.x, a0.y + a1.y, a0.z + a1.z, a0.w + a1.w);
            a.x += __shfl_xor_sync(FULL, a.x, 8); a.x += __shfl_xor_sync(FULL, a.x, 16);
            a.y += __shfl_xor_sync(FULL, a.y, 8); a.y += __shfl_xor_sync(FULL, a.y, 16);
            a.z += __shfl_xor_sync(FULL, a.z, 8); a.z += __shfl_xor_sync(FULL, a.z, 16);
            a.w += __shfl_xor_sync(FULL, a.w, 8); a.w += __shfl_xor_sync(FULL, a.w, 16);
            if (lane < 8) *(float4*)&sm->aggb[w*32 + lane*4] = a;
            __syncwarp();

            float o = sm->br[lane];
#pragma unroll
            for (int c = 0; c < 8; c++) {
                float4 wrv = *(const float4*)&sm->wr[lane*WSTR + 4*c];
                float4 wov = *(const float4*)&sm->wo[lane*WSTR + 4*c];
                float4 av  = *(const float4*)&sm->aggb[w*32 + 4*c];
                float4 hv  = *(const float4*)&sm->h1[u*32 + 4*c];
                o += av.x*wrv.x + hv.x*wov.x;
                o += av.y*wrv.y + hv.y*wov.y;
                o += av.z*wrv.z + hv.z*wov.z;
                o += av.w*wrv.w + hv.w*wov.w;
            }
            sm->hcb[w*32 + lane] = o;
            __syncwarp();

            int lk = lane & 15;
            float sl = sm->bp[lk];
#pragma unroll
            for (int c = 0; c < 8; c++) {
                float4 wpv = *(const float4*)&sm->wp[lk*WSTR + 4*c];
                float4 hq  = *(const float4*)&sm->hcb[w*32 + 4*c];
                sl += hq.x*wpv.x + hq.y*wpv.y + hq.z*wpv.z + hq.w*wpv.w;
            }
            float m = sl;
#pragma unroll
            for (int off = 8; off >= 1; off >>= 1)
                m = fmaxf(m, __shfl_xor_sync(FULL, m, off, 16));
            float e = expf(sl - m);
            float sum = e;
#pragma unroll
            for (int off = 8; off >= 1; off >>= 1)
                sum += __shfl_xor_sync(FULL, sum, off, 16);
            float svx = e / sum;
            if (lane < 16) sm->s[u*16 + lk] = svx;

#pragma unroll
            for (int k = 0; k < 16; k++) {
                float sk = __shfl_sync(FULL, svx, k);
                px_reg[k] += sk * o;
            }
        }
    }
    __syncthreads();

    // ---- px reduction across 8 warps ----
    for (int round = 0; round < 2; round++) {
        if ((w >> 2) == round) {
            int wl = w & 3;
#pragma unroll
            for (int k = 0; k < 16; k++)
                sm->buf[wl*512 + k*32 + lane] = px_reg[k];
        }
        __syncthreads();
        for (int i = tid; i < 512; i += 256) {
            float v = sm->buf[i] + sm->buf[512+i] + sm->buf[1024+i] + sm->buf[1536+i];
            if (round == 0) sm->px[i] = v; else sm->px[i] += v;
        }
        __syncthreads();
    }

    // ---- Phase B: t = A@s (MLP=2); out_adj = s^T t, ss = s^T s, den ----
    float oa[8], ob[8];
#pragma unroll
    for (int i = 0; i < 8; i++) { oa[i] = 0.f; ob[i] = 0.f; }
    float den_acc = 0.f;
    {
        int grp8 = lane >> 2, q4 = lane & 3;
        int j = lane & 15, kh = lane >> 4;
        const float4* ssr = (const float4*)sm->s;
        for (int u = w*32; u < w*32 + 32; u++) {
            int d  = sm->deg[u];
            int st = sm->start[u];
            float4 a0 = make_float4(0.f, 0.f, 0.f, 0.f);
            float4 a1 = make_float4(0.f, 0.f, 0.f, 0.f);
            int i = grp8;
            for (; i + 8 < d; i += 16) {
                int v0 = sm->idx[st + i];
                int v1 = sm->idx[st + i + 8];
                float4 r0 = ssr[v0*4 + q4];
                float4 r1 = ssr[v1*4 + q4];
                a0.x += r0.x; a0.y += r0.y; a0.z += r0.z; a0.w += r0.w;
                a1.x += r1.x; a1.y += r1.y; a1.z += r1.z; a1.w += r1.w;
            }
            if (i < d) {
                int v0 = sm->idx[st + i];
                float4 r0 = ssr[v0*4 + q4];
                a0.x += r0.x; a0.y += r0.y; a0.z += r0.z; a0.w += r0.w;
            }
            float4 a = make_float4(a0.x + a1.x, a0.y + a1.y, a0.z + a1.z, a0.w + a1.w);
            a.x += __shfl_xor_sync(FULL, a.x, 4); a.x += __shfl_xor_sync(FULL, a.x, 8); a.x += __shfl_xor_sync(FULL, a.x, 16);
            a.y += __shfl_xor_sync(FULL, a.y, 4); a.y += __shfl_xor_sync(FULL, a.y, 8); a.y += __shfl_xor_sync(FULL, a.y, 16);
            a.z += __shfl_xor_sync(FULL, a.z, 4); a.z += __shfl_xor_sync(FULL, a.z, 8); a.z += __shfl_xor_sync(FULL, a.z, 16);
            a.w += __shfl_xor_sync(FULL, a.w, 4); a.w += __shfl_xor_sync(FULL, a.w, 8); a.w += __shfl_xor_sync(FULL, a.w, 16);
            if (lane < 4) *(float4*)&sm->tbuf[w*16 + lane*4] = a;
            __syncwarp();
            float tj = sm->tbuf[w*16 + j];
            float sj = sm->s[u*16 + j];
            __syncwarp();

            float v2 = sj*sj;
            v2 += __shfl_xor_sync(FULL, v2, 1, 16);
            v2 += __shfl_xor_sync(FULL, v2, 2, 16);
            v2 += __shfl_xor_sync(FULL, v2, 4, 16);
            v2 += __shfl_xor_sync(FULL, v2, 8, 16);
            den_acc += (float)d * v2;

#pragma unroll
            for (int kk = 0; kk < 8; kk++) {
                float su = sm->s[u*16 + kh*8 + kk];
                oa[kk] += su * tj;
                ob[kk] += su * sj;
            }
        }
    }
    __syncthreads();

    // ---- reduce out_adj, ss, den across warps ----
    {
        int j = lane & 15, kh = lane >> 4;
#pragma unroll
        for (int kk = 0; kk < 8; kk++)
            sm->buf[w*256 + (kh*8+kk)*16 + j] = oa[kk];
        if (lane == 0) sm->red[w] = den_acc;
        __syncthreads();
        float v = 0.f;
#pragma unroll
        for (int ww = 0; ww < 8; ww++) v += sm->buf[ww*256 + tid];
        sm->adj[tid] = v;
        __syncthreads();
#pragma unroll
        for (int kk = 0; kk < 8; kk++)
            sm->buf[w*256 + (kh*8+kk)*16 + j] = ob[kk];
        __syncthreads();
        float v2 = 0.f;
#pragma unroll
        for (int ww = 0; ww < 8; ww++) v2 += sm->buf[ww*256 + tid];
        sm->ssm[tid] = v2;
        __syncthreads();
    }

    // ---- losses (CTA partials; global atomic reduce at the end) ----
    int kq = tid >> 4, jq = tid & 15;
    float mincut_part = 0.f;
    if (tid == 0) {
        float den = 0.f;
        for (int i = 0; i < 8; i++) den += sm->red[i];
        float num = 0.f;
        for (int kk = 0; kk < K; kk++) num += sm->adj[kk*K + kk];
        mincut_part = -(num / den);
    }
    float ssv = sm->ssm[tid];
    sm->buf[tid] = ssv * ssv;
    __syncthreads();
    for (int off = 128; off > 0; off >>= 1) { if (tid < off) sm->buf[tid] += sm->buf[tid + off]; __syncthreads(); }
    float nrm = sqrtf(sm->buf[0]);
    __syncthreads();
    float diff = ssv / nrm - ((kq == jq) ? 0.25f : 0.f);
    sm->buf[tid] = diff * diff;
    __syncthreads();
    for (int off = 128; off > 0; off >>= 1) { if (tid < off) sm->buf[tid] += sm->buf[tid + off]; __syncthreads(); }
    float ortho_part = (tid == 0) ? sqrtf(sm->buf[0]) : 0.f;
    __syncthreads();

    // ---- normalize out_adj ----
    {
        float av = (kq == jq) ? 0.f : sm->adj[tid];
        sm->adj[tid] = av;
    }
    __syncthreads();
    if (tid < K) {
        float rs = 0.f;
        for (int jj = 0; jj < K; jj++) rs += sm->adj[tid*K + jj];
        sm->sd[tid] = sqrtf(rs) + EPSF;
    }
    __syncthreads();
    sm->adj[tid] = sm->adj[tid] / (sm->sd[kq] * sm->sd[jq]);
    __syncthreads();

    // ---- conv2 on pooled features ----
    {
        int h = tid & 31, kk0 = tid >> 5;
#pragma unroll
        for (int rep = 0; rep < 2; rep++) {
            int kc = kk0 + rep*8;
            float m1 = 0.f;
#pragma unroll
            for (int jj = 0; jj < K; jj++) m1 += sm->adj[kc*K + jj] * sm->px[jj*H + h];
            sm->buf[kc*H + h] = m1;
        }
    }
    __syncthreads();
    {
        int h = tid & 31, kk0 = tid >> 5;
#pragma unroll
        for (int rep = 0; rep < 2; rep++) {
            int kc = kk0 + rep*8;
            float acc = brel2[h];
            for (int c = 0; c < H; c++)
                acc += sm->buf[kc*H + c] * Wrel2[c*H + h] + sm->px[kc*H + c] * Wroot2[c*H + h];
            sm->buf[512 + kc*H + h] = acc;
        }
    }
    __syncthreads();

    // ---- readout + MLP + log_softmax ----
    if (tid < H) {
        float r = 0.f;
#pragma unroll
        for (int kk = 0; kk < K; kk++) r += sm->buf[512 + kk*H + tid];
        sm->sr[tid] = r;
    }
    __syncthreads();
    if (tid < H) {
        float a2 = blin2[tid];
        for (int c = 0; c < H; c++) a2 += sm->sr[c] * Wlin2[c*H + tid];
        sm->sh3[tid] = fmaxf(a2, 0.f);
    }
    __syncthreads();
    if (tid < FOUT) {
        float a3 = blin3[tid];
        for (int c = 0; c < H; c++) a3 += sm->sh3[c] * Wlin3[c*FOUT + tid];
        sm->so[tid] = a3;
    }
    __syncthreads();
    if (tid == 0) {
        float m = sm->so[0];
        for (int i = 1; i < FOUT; i++) m = fmaxf(m, sm->so[i]);
        float s = 0.f;
        for (int i = 0; i < FOUT; i++) s += expf(sm->so[i] - m);
        float lse = m + logf(s);
        for (int i = 0; i < FOUT; i++) out[b*FOUT + i] = sm->so[i] - lse;

        // global loss reduction; last CTA writes + resets (graph-replay safe)
        atomicAdd(&g_acc[0], mincut_part * (1.f/(float)B));
        atomicAdd(&g_acc[1], ortho_part  * (1.f/(float)B));
        __threadfence();
        int old = atomicAdd(&g_ctr, 1);
        if (old == B - 1) {
            __threadfence();
            float l0 = g_acc[0], l1 = g_acc[1];
            if (out_size > B*FOUT)     out[B*FOUT]     = l0;
            if (out_size > B*FOUT + 1) out[B*FOUT + 1] = l1;
            g_acc[0] = 0.f; g_acc[1] = 0.f;
            g_ctr = 0;
            __threadfence();
        }
    }
}

// ---------------- launch ----------------
extern "C" void kernel_launch(void* const* d_in, const int* in_sizes, int n_in,
                              void* d_out, int out_size) {
    const float* x     = (const float*)d_in[0];
    const int*   ei    = (const int*)d_in[1];
    const float* Wlin1 = (const float*)d_in[3];
    const float* blin1 = (const float*)d_in[4];
    const float* Wrel1 = (const float*)d_in[5];
    const float* brel1 = (const float*)d_in[6];
    const float* Wroot1= (const float*)d_in[7];
    const float* Wpool = (const float*)d_in[8];
    const float* bpool = (const float*)d_in[9];
    const float* Wrel2 = (const float*)d_in[10];
    const float* brel2 = (const float*)d_in[11];
    const float* Wroot2= (const float*)d_in[12];
    const float* Wlin2 = (const float*)d_in[13];
    const float* blin2 = (const float*)d_in[14];
    const float* Wlin3 = (const float*)d_in[15];
    const float* blin3 = (const float*)d_in[16];
    float* out = (float*)d_out;

    cudaFuncSetAttribute(k_mega, cudaFuncAttributeMaxDynamicSharedMemorySize,
                         (int)sizeof(SMem));

    k_mega<<<B, 256, sizeof(SMem)>>>(x, ei, Wlin1, blin1,
                                     Wrel1, brel1, Wroot1, Wpool, bpool,
                                     Wrel2, brel2, Wroot2,
                                     Wlin2, blin2, Wlin3, blin3, out, out_size);
}

// round 9
// speedup vs baseline: 1.0272x; 1.0272x over previous
#include <cuda_runtime.h>

#define B 512
#define N 256
#define E_PER 8192
#define NT (B*N)
#define ET (B*E_PER)
#define FIN 128
#define H 32
#define K 16
#define FOUT 10
#define EPSF 1e-15f
#define FULL 0xffffffffu
#define WSTR 36         // padded transposed-weight stride
#define RS   260        // xs transpose stride
#define NTHR 512
#define NW   16         // warps per CTA
#define NPW  16         // nodes per warp

// ---------------- globals ----------------
__device__ float g_acc[2] = {0.f, 0.f};
__device__ int   g_ctr = 0;

// ---------------- f32x2 helpers ----------------
__device__ __forceinline__ unsigned long long pk2(float lo, float hi) {
    unsigned long long r;
    asm("mov.b64 %0, {%1,%2};" : "=l"(r)
        : "r"(__float_as_uint(lo)), "r"(__float_as_uint(hi)));
    return r;
}
__device__ __forceinline__ void fma2(unsigned long long& d,
                                     unsigned long long a, unsigned long long b) {
    asm("fma.rn.f32x2 %0, %1, %2, %0;" : "+l"(d) : "l"(a), "l"(b));
}
__device__ __forceinline__ void upk2(float& lo, float& hi, unsigned long long v) {
    unsigned int a, b2;
    asm("mov.b64 {%0,%1}, %2;" : "=r"(a), "=r"(b2) : "l"(v));
    lo = __uint_as_float(a); hi = __uint_as_float(b2);
}

// ---------------- mega-kernel shared layout ----------------
struct SMem {
    float h1[N*H];            // 32768 B
    float s[N*K];             // 16384 B (overlaid by ws[FIN*H] during lin1)
    float buf[2048];          // 8192  B
    float wr[H*WSTR];
    float wo[H*WSTR];
    float wp[K*WSTR];
    float aggb[NW*32];
    float hcb[NW*32];
    float br[H];
    float bp[K];
    float px[K*H];
    float adj[K*K];
    float ssm[K*K];
    float red[32];
    float tbuf[NW*16];
    float sd[K];
    float sr[H];
    float sh3[H];
    float so[FOUT];
    alignas(16) unsigned short idx[E_PER];  // overlaid by xs[16*RS] during lin1
    int deg[N];               // xs overlay spills 256B into deg (rewritten later)
    int start[N];
    int cnt[N];
};

// ---------------- mega: entire network, one CTA per graph, 512 threads ------
__global__ __launch_bounds__(NTHR, 2)
void k_mega(const float* __restrict__ x,
            const int* __restrict__ ei,
            const float* __restrict__ Wlin1, const float* __restrict__ blin1,
            const float* __restrict__ Wrel,  const float* __restrict__ brel,
            const float* __restrict__ Wroot, const float* __restrict__ Wpool,
            const float* __restrict__ bpool,
            const float* __restrict__ Wrel2, const float* __restrict__ brel2,
            const float* __restrict__ Wroot2,
            const float* __restrict__ Wlin2, const float* __restrict__ blin2,
            const float* __restrict__ Wlin3, const float* __restrict__ blin3,
            float* __restrict__ out, int out_size)
{
    extern __shared__ char smraw[];
    SMem* sm = (SMem*)smraw;
    int b = blockIdx.x, tid = threadIdx.x;
    int w = tid >> 5, lane = tid & 31;
    int base = b * N;

    // ---- stage conv/pool weights early ----
    for (int i = tid; i < H*H; i += NTHR) {
        int k = i >> 5, l = i & 31;
        sm->wr[l*WSTR + k] = Wrel[i];
        sm->wo[l*WSTR + k] = Wroot[i];
    }
    for (int i = tid; i < H*K; i += NTHR) {
        int k = i >> 4, l = i & 15;
        sm->wp[l*WSTR + k] = Wpool[i];
    }
    if (tid < H) sm->br[tid] = brel[tid];
    if (tid < K) sm->bp[tid] = bpool[tid];
    if (tid < N) sm->cnt[tid] = 0;

    // ================= fused lin1: h1 = x[b] @ W1 + b1 (FFMA2 tile) ==========
    {
        float* ws = sm->s;                 // overlay
        float* xs = (float*)sm->idx;       // overlay
        for (int i = tid; i < FIN*H; i += NTHR) ws[i] = Wlin1[i];

        int c0 = (tid & 7) * 4;            // 4 output cols
        int r0 = (tid >> 3) * 4;           // 4 output rows (2 packed pairs)
        int lr = tid >> 2;                 // staging rows lr, lr+128
        int q  = tid & 3;                  // staging k-quad

        float bsv[4];
#pragma unroll
        for (int c = 0; c < 4; c++) bsv[c] = blin1[c0 + c];

        const float* xg = x + (size_t)base * FIN;
        float4 nx[2];
#pragma unroll
        for (int p = 0; p < 2; p++)
            nx[p] = *(const float4*)&xg[(size_t)(lr + p*128)*FIN + q*4];

        unsigned long long acc[2][4];
#pragma unroll
        for (int pr = 0; pr < 2; pr++)
#pragma unroll
            for (int c = 0; c < 4; c++)
                acc[pr][c] = pk2(bsv[c], bsv[c]);

        for (int kt = 0; kt < 8; kt++) {
            __syncthreads();
#pragma unroll
            for (int p = 0; p < 2; p++) {
                int row = lr + p*128;
                xs[(q*4+0)*RS + row] = nx[p].x;
                xs[(q*4+1)*RS + row] = nx[p].y;
                xs[(q*4+2)*RS + row] = nx[p].z;
                xs[(q*4+3)*RS + row] = nx[p].w;
            }
            __syncthreads();
            if (kt < 7) {
#pragma unroll
                for (int p = 0; p < 2; p++)
                    nx[p] = *(const float4*)&xg[(size_t)(lr + p*128)*FIN + (kt+1)*16 + q*4];
            }
#pragma unroll
            for (int k = 0; k < 16; k++) {
                float4 wv = *(const float4*)&ws[(kt*16 + k)*H + c0];
                float4 xa = *(const float4*)&xs[k*RS + r0];
                unsigned long long xp[2], wp2[4];
                xp[0] = pk2(xa.x, xa.y); xp[1] = pk2(xa.z, xa.w);
                wp2[0] = pk2(wv.x, wv.x); wp2[1] = pk2(wv.y, wv.y);
                wp2[2] = pk2(wv.z, wv.z); wp2[3] = pk2(wv.w, wv.w);
#pragma unroll
                for (int pr = 0; pr < 2; pr++) {
                    fma2(acc[pr][0], xp[pr], wp2[0]);
                    fma2(acc[pr][1], xp[pr], wp2[1]);
                    fma2(acc[pr][2], xp[pr], wp2[2]);
                    fma2(acc[pr][3], xp[pr], wp2[3]);
                }
            }
        }
#pragma unroll
        for (int pr = 0; pr < 2; pr++) {
            float lo[4], hi[4];
#pragma unroll
            for (int c = 0; c < 4; c++) upk2(lo[c], hi[c], acc[pr][c]);
            int gr = r0 + 2*pr;
            *(float4*)&sm->h1[gr*H + c0]     = make_float4(lo[0], lo[1], lo[2], lo[3]);
            *(float4*)&sm->h1[(gr+1)*H + c0] = make_float4(hi[0], hi[1], hi[2], hi[3]);
        }
    }
    __syncthreads();

    // ---- sort edges by src ----
    const int* srcg = ei + b*E_PER;
    const int* dstg = ei + ET + b*E_PER;
#pragma unroll
    for (int i = 0; i < E_PER/NTHR; i++)
        atomicAdd(&sm->cnt[srcg[tid + i*NTHR] - base], 1);
    __syncthreads();
    int d0 = 0;
    if (tid < N) { d0 = sm->cnt[tid]; sm->start[tid] = d0; }
    __syncthreads();
    for (int off = 1; off < N; off <<= 1) {
        int v = 0;
        if (tid < N && tid >= off) v = sm->start[tid - off];
        __syncthreads();
        if (tid < N) sm->start[tid] += v;
        __syncthreads();
    }
    if (tid < N) {
        int st0 = sm->start[tid] - d0;
        sm->deg[tid] = d0;
        sm->start[tid] = st0;
        sm->cnt[tid] = st0;
    }
    __syncthreads();
#pragma unroll
    for (int i = 0; i < E_PER/NTHR; i++) {
        int u = srcg[tid + i*NTHR] - base;
        int p = atomicAdd(&sm->cnt[u], 1);
        sm->idx[p] = (unsigned short)(dstg[tid + i*NTHR] - base);
    }
    __syncthreads();

    // ---- Phase A: gather agg (MLP=2), conv1, pool, softmax, px rank-1 ----
    float px_reg[16];
#pragma unroll
    for (int k = 0; k < 16; k++) px_reg[k] = 0.f;

    {
        int grp = lane >> 3, q8 = lane & 7;
        const float4* h1r = (const float4*)sm->h1;
        for (int u = w*NPW; u < w*NPW + NPW; u++) {
            int d  = sm->deg[u];
            int st = sm->start[u];
            float4 a0 = make_float4(0.f, 0.f, 0.f, 0.f);
            float4 a1 = make_float4(0.f, 0.f, 0.f, 0.f);
            int i = grp;
            for (; i + 4 < d; i += 8) {
                int v0 = sm->idx[st + i];
                int v1 = sm->idx[st + i + 4];
                float4 r0 = h1r[v0*8 + q8];
                float4 r1 = h1r[v1*8 + q8];
                a0.x += r0.x; a0.y += r0.y; a0.z += r0.z; a0.w += r0.w;
                a1.x += r1.x; a1.y += r1.y; a1.z += r1.z; a1.w += r1.w;
            }
            if (i < d) {
                int v0 = sm->idx[st + i];
                float4 r0 = h1r[v0*8 + q8];
                a0.x += r0.x; a0.y += r0.y; a0.z += r0.z; a0.w += r0.w;
            }
            float4 a = make_float4(a0.x + a1.x, a0.y + a1.y, a0.z + a1.z, a0.w + a1.w);
            a.x += __shfl_xor_sync(FULL, a.x, 8); a.x += __shfl_xor_sync(FULL, a.x, 16);
            a.y += __shfl_xor_sync(FULL, a.y, 8); a.y += __shfl_xor_sync(FULL, a.y, 16);
            a.z += __shfl_xor_sync(FULL, a.z, 8); a.z += __shfl_xor_sync(FULL, a.z, 16);
            a.w += __shfl_xor_sync(FULL, a.w, 8); a.w += __shfl_xor_sync(FULL, a.w, 16);
            if (lane < 8) *(float4*)&sm->aggb[w*32 + lane*4] = a;
            __syncwarp();

            float o = sm->br[lane];
#pragma unroll
            for (int c = 0; c < 8; c++) {
                float4 wrv = *(const float4*)&sm->wr[lane*WSTR + 4*c];
                float4 wov = *(const float4*)&sm->wo[lane*WSTR + 4*c];
                float4 av  = *(const float4*)&sm->aggb[w*32 + 4*c];
                float4 hv  = *(const float4*)&sm->h1[u*32 + 4*c];
                o += av.x*wrv.x + hv.x*wov.x;
                o += av.y*wrv.y + hv.y*wov.y;
                o += av.z*wrv.z + hv.z*wov.z;
                o += av.w*wrv.w + hv.w*wov.w;
            }
            sm->hcb[w*32 + lane] = o;
            __syncwarp();

            int lk = lane & 15;
            float sl = sm->bp[lk];
#pragma unroll
            for (int c = 0; c < 8; c++) {
                float4 wpv = *(const float4*)&sm->wp[lk*WSTR + 4*c];
                float4 hq  = *(const float4*)&sm->hcb[w*32 + 4*c];
                sl += hq.x*wpv.x + hq.y*wpv.y + hq.z*wpv.z + hq.w*wpv.w;
            }
            float m = sl;
#pragma unroll
            for (int off = 8; off >= 1; off >>= 1)
                m = fmaxf(m, __shfl_xor_sync(FULL, m, off, 16));
            float e = expf(sl - m);
            float sum = e;
#pragma unroll
            for (int off = 8; off >= 1; off >>= 1)
                sum += __shfl_xor_sync(FULL, sum, off, 16);
            float svx = e / sum;
            if (lane < 16) sm->s[u*16 + lk] = svx;

#pragma unroll
            for (int k = 0; k < 16; k++) {
                float sk = __shfl_sync(FULL, svx, k);
                px_reg[k] += sk * o;
            }
        }
    }
    __syncthreads();

    // ---- px reduction across 16 warps (4 rounds of 4 via buf) ----
    for (int round = 0; round < 4; round++) {
        if ((w >> 2) == round) {
            int wl = w & 3;
#pragma unroll
            for (int k = 0; k < 16; k++)
                sm->buf[wl*512 + k*32 + lane] = px_reg[k];
        }
        __syncthreads();
        if (tid < 512) {
            float v = sm->buf[tid] + sm->buf[512+tid] + sm->buf[1024+tid] + sm->buf[1536+tid];
            if (round == 0) sm->px[tid] = v; else sm->px[tid] += v;
        }
        __syncthreads();
    }

    // ---- Phase B: t = A@s (MLP=2); out_adj = s^T t, ss = s^T s, den ----
    float oa[8], ob[8];
#pragma unroll
    for (int i = 0; i < 8; i++) { oa[i] = 0.f; ob[i] = 0.f; }
    float den_acc = 0.f;
    {
        int grp8 = lane >> 2, q4 = lane & 3;
        int j = lane & 15, kh = lane >> 4;
        const float4* ssr = (const float4*)sm->s;
        for (int u = w*NPW; u < w*NPW + NPW; u++) {
            int d  = sm->deg[u];
            int st = sm->start[u];
            float4 a0 = make_float4(0.f, 0.f, 0.f, 0.f);
            float4 a1 = make_float4(0.f, 0.f, 0.f, 0.f);
            int i = grp8;
            for (; i + 8 < d; i += 16) {
                int v0 = sm->idx[st + i];
                int v1 = sm->idx[st + i + 8];
                float4 r0 = ssr[v0*4 + q4];
                float4 r1 = ssr[v1*4 + q4];
                a0.x += r0.x; a0.y += r0.y; a0.z += r0.z; a0.w += r0.w;
                a1.x += r1.x; a1.y += r1.y; a1.z += r1.z; a1.w += r1.w;
            }
            if (i < d) {
                int v0 = sm->idx[st + i];
                float4 r0 = ssr[v0*4 + q4];
                a0.x += r0.x; a0.y += r0.y; a0.z += r0.z; a0.w += r0.w;
            }
            float4 a = make_float4(a0.x + a1.x, a0.y + a1.y, a0.z + a1.z, a0.w + a1.w);
            a.x += __shfl_xor_sync(FULL, a.x, 4); a.x += __shfl_xor_sync(FULL, a.x, 8); a.x += __shfl_xor_sync(FULL, a.x, 16);
            a.y += __shfl_xor_sync(FULL, a.y, 4); a.y += __shfl_xor_sync(FULL, a.y, 8); a.y += __shfl_xor_sync(FULL, a.y, 16);
            a.z += __shfl_xor_sync(FULL, a.z, 4); a.z += __shfl_xor_sync(FULL, a.z, 8); a.z += __shfl_xor_sync(FULL, a.z, 16);
            a.w += __shfl_xor_sync(FULL, a.w, 4); a.w += __shfl_xor_sync(FULL, a.w, 8); a.w += __shfl_xor_sync(FULL, a.w, 16);
            if (lane < 4) *(float4*)&sm->tbuf[w*16 + lane*4] = a;
            __syncwarp();
            float tj = sm->tbuf[w*16 + j];
            float sj = sm->s[u*16 + j];
            __syncwarp();

            float v2 = sj*sj;
            v2 += __shfl_xor_sync(FULL, v2, 1, 16);
            v2 += __shfl_xor_sync(FULL, v2, 2, 16);
            v2 += __shfl_xor_sync(FULL, v2, 4, 16);
            v2 += __shfl_xor_sync(FULL, v2, 8, 16);
            den_acc += (float)d * v2;

#pragma unroll
            for (int kk = 0; kk < 8; kk++) {
                float su = sm->s[u*16 + kh*8 + kk];
                oa[kk] += su * tj;
                ob[kk] += su * sj;
            }
        }
    }
    __syncthreads();

    // ---- reduce out_adj, ss, den across 16 warps (2 rounds of 8) ----
    {
        int j = lane & 15, kh = lane >> 4;
        if (lane == 0) sm->red[w] = den_acc;
        for (int round = 0; round < 2; round++) {
            if ((w >> 3) == round) {
#pragma unroll
                for (int kk = 0; kk < 8; kk++)
                    sm->buf[(w & 7)*256 + (kh*8+kk)*16 + j] = oa[kk];
            }
            __syncthreads();
            if (tid < 256) {
                float v = 0.f;
#pragma unroll
                for (int ww = 0; ww < 8; ww++) v += sm->buf[ww*256 + tid];
                if (round == 0) sm->adj[tid] = v; else sm->adj[tid] += v;
            }
            __syncthreads();
        }
        for (int round = 0; round < 2; round++) {
            if ((w >> 3) == round) {
#pragma unroll
                for (int kk = 0; kk < 8; kk++)
                    sm->buf[(w & 7)*256 + (kh*8+kk)*16 + j] = ob[kk];
            }
            __syncthreads();
            if (tid < 256) {
                float v = 0.f;
#pragma unroll
                for (int ww = 0; ww < 8; ww++) v += sm->buf[ww*256 + tid];
                if (round == 0) sm->ssm[tid] = v; else sm->ssm[tid] += v;
            }
            __syncthreads();
        }
    }

    // ---- losses (CTA partials -> global atomics) ----
    int kq = (tid >> 4) & 15, jq = tid & 15;
    float mincut_part = 0.f;
    if (tid == 0) {
        float den = 0.f;
        for (int i = 0; i < NW; i++) den += sm->red[i];
        float num = 0.f;
        for (int kk = 0; kk < K; kk++) num += sm->adj[kk*K + kk];
        mincut_part = -(num / den);
    }
    float ssv = (tid < 256) ? sm->ssm[tid] : 0.f;
    if (tid < 256) sm->buf[tid] = ssv * ssv;
    __syncthreads();
    for (int off = 128; off > 0; off >>= 1) { if (tid < off) sm->buf[tid] += sm->buf[tid + off]; __syncthreads(); }
    float nrm = sqrtf(sm->buf[0]);
    __syncthreads();
    if (tid < 256) {
        float diff = ssv / nrm - ((kq == jq) ? 0.25f : 0.f);
        sm->buf[tid] = diff * diff;
    }
    __syncthreads();
    for (int off = 128; off > 0; off >>= 1) { if (tid < off) sm->buf[tid] += sm->buf[tid + off]; __syncthreads(); }
    float ortho_part = (tid == 0) ? sqrtf(sm->buf[0]) : 0.f;
    __syncthreads();

    // ---- normalize out_adj ----
    if (tid < 256) {
        float av = (kq == jq) ? 0.f : sm->adj[tid];
        sm->adj[tid] = av;
    }
    __syncthreads();
    if (tid < K) {
        float rs = 0.f;
        for (int jj = 0; jj < K; jj++) rs += sm->adj[tid*K + jj];
        sm->sd[tid] = sqrtf(rs) + EPSF;
    }
    __syncthreads();
    if (tid < 256) sm->adj[tid] = sm->adj[tid] / (sm->sd[kq] * sm->sd[jq]);
    __syncthreads();

    // ---- conv2 on pooled features (one (kc,h) per thread) ----
    {
        int h = tid & 31, kc = tid >> 5;   // kc 0..15
        float m1 = 0.f;
#pragma unroll
        for (int jj = 0; jj < K; jj++) m1 += sm->adj[kc*K + jj] * sm->px[jj*H + h];
        sm->buf[kc*H + h] = m1;
    }
    __syncthreads();
    {
        int h = tid & 31, kc = tid >> 5;
        float acc = brel2[h];
        for (int c = 0; c < H; c++)
            acc += sm->buf[kc*H + c] * Wrel2[c*H + h] + sm->px[kc*H + c] * Wroot2[c*H + h];
        sm->buf[512 + kc*H + h] = acc;
    }
    __syncthreads();

    // ---- readout + MLP + log_softmax ----
    if (tid < H) {
        float r = 0.f;
#pragma unroll
        for (int kk = 0; kk < K; kk++) r += sm->buf[512 + kk*H + tid];
        sm->sr[tid] = r;
    }
    __syncthreads();
    if (tid < H) {
        float a2 = blin2[tid];
        for (int c = 0; c < H; c++) a2 += sm->sr[c] * Wlin2[c*H + tid];
        sm->sh3[tid] = fmaxf(a2, 0.f);
    }
    __syncthreads();
    if (tid < FOUT) {
        float a3 = blin3[tid];
        for (int c = 0; c < H; c++) a3 += sm->sh3[c] * Wlin3[c*FOUT + tid];
        sm->so[tid] = a3;
    }
    __syncthreads();
    if (tid == 0) {
        float m = sm->so[0];
        for (int i = 1; i < FOUT; i++) m = fmaxf(m, sm->so[i]);
        float s = 0.f;
        for (int i = 0; i < FOUT; i++) s += expf(sm->so[i] - m);
        float lse = m + logf(s);
        for (int i = 0; i < FOUT; i++) out[b*FOUT + i] = sm->so[i] - lse;

        // global loss reduction; last CTA writes + resets (graph-replay safe)
        atomicAdd(&g_acc[0], mincut_part * (1.f/(float)B));
        atomicAdd(&g_acc[1], ortho_part  * (1.f/(float)B));
        __threadfence();
        int old = atomicAdd(&g_ctr, 1);
        if (old == B - 1) {
            __threadfence();
            float l0 = g_acc[0], l1 = g_acc[1];
            if (out_size > B*FOUT)     out[B*FOUT]     = l0;
            if (out_size > B*FOUT + 1) out[B*FOUT + 1] = l1;
            g_acc[0] = 0.f; g_acc[1] = 0.f;
            g_ctr = 0;
            __threadfence();
        }
    }
}

// ---------------- launch ----------------
extern "C" void kernel_launch(void* const* d_in, const int* in_sizes, int n_in,
                              void* d_out, int out_size) {
    const float* x     = (const float*)d_in[0];
    const int*   ei    = (const int*)d_in[1];
    const float* Wlin1 = (const float*)d_in[3];
    const float* blin1 = (const float*)d_in[4];
    const float* Wrel1 = (const float*)d_in[5];
    const float* brel1 = (const float*)d_in[6];
    const float* Wroot1= (const float*)d_in[7];
    const float* Wpool = (const float*)d_in[8];
    const float* bpool = (const float*)d_in[9];
    const float* Wrel2 = (const float*)d_in[10];
    const float* brel2 = (const float*)d_in[11];
    const float* Wroot2= (const float*)d_in[12];
    const float* Wlin2 = (const float*)d_in[13];
    const float* blin2 = (const float*)d_in[14];
    const float* Wlin3 = (const float*)d_in[15];
    const float* blin3 = (const float*)d_in[16];
    float* out = (float*)d_out;

    cudaFuncSetAttribute(k_mega, cudaFuncAttributeMaxDynamicSharedMemorySize,
                         (int)sizeof(SMem));

    k_mega<<<B, NTHR, sizeof(SMem)>>>(x, ei, Wlin1, blin1,
                                      Wrel1, brel1, Wroot1, Wpool, bpool,
                                      Wrel2, brel2, Wroot2,
                                      Wlin2, blin2, Wlin3, blin3, out, out_size);
}

// round 11
// speedup vs baseline: 1.2045x; 1.1727x over previous
#include <cuda_runtime.h>

#define B 512
#define N 256
#define E_PER 8192
#define NT (B*N)
#define ET (B*E_PER)
#define FIN 128
#define H 32
#define K 16
#define FOUT 10
#define EPSF 1e-15f
#define FULL 0xffffffffu
#define WSTR 36         // padded transposed-weight stride
#define RS   260        // xs transpose stride
#define NTHR 512
#define NW   16         // warps per CTA
#define NPW  16         // nodes per warp

// ---------------- globals ----------------
__device__ float g_acc[2] = {0.f, 0.f};
__device__ int   g_ctr = 0;

// ---------------- f32x2 helpers ----------------
__device__ __forceinline__ unsigned long long pk2(float lo, float hi) {
    unsigned long long r;
    asm("mov.b64 %0, {%1,%2};" : "=l"(r)
        : "r"(__float_as_uint(lo)), "r"(__float_as_uint(hi)));
    return r;
}
__device__ __forceinline__ void fma2(unsigned long long& d,
                                     unsigned long long a, unsigned long long b) {
    asm("fma.rn.f32x2 %0, %1, %2, %0;" : "+l"(d) : "l"(a), "l"(b));
}
__device__ __forceinline__ void upk2(float& lo, float& hi, unsigned long long v) {
    unsigned int a, b2;
    asm("mov.b64 {%0,%1}, %2;" : "=r"(a), "=r"(b2) : "l"(v));
    lo = __uint_as_float(a); hi = __uint_as_float(b2);
}

// ---------------- mega-kernel shared layout ----------------
struct SMem {
    float h1[N*H];            // 32768 B
    float s[N*K];             // 16384 B (overlaid by ws[FIN*H] during lin1)
    float wk[4096];           // 16384 B: aggb/hcb strips, reductions, conv2
    float wr[H*WSTR];
    float wo[H*WSTR];
    float wp[K*WSTR];
    float br[H];
    float bp[K];
    float px[K*H];
    float adj[K*K];
    float ssm[K*K];
    float red[32];
    float tbuf[NW*16];
    float sd[K];
    float sr[H];
    float sh3[H];
    float so[FOUT];
    alignas(16) unsigned short idx[E_PER];  // overlaid by xs[16*RS] during lin1
    int deg[N];               // xs overlay spills 256B into deg (rewritten later)
    int start[N];
    int cnt[N];
};

// ---------------- mega: entire network, one CTA per graph, 512 threads ------
__global__ __launch_bounds__(NTHR, 2)
void k_mega(const float* __restrict__ x,
            const int* __restrict__ ei,
            const float* __restrict__ Wlin1, const float* __restrict__ blin1,
            const float* __restrict__ Wrel,  const float* __restrict__ brel,
            const float* __restrict__ Wroot, const float* __restrict__ Wpool,
            const float* __restrict__ bpool,
            const float* __restrict__ Wrel2, const float* __restrict__ brel2,
            const float* __restrict__ Wroot2,
            const float* __restrict__ Wlin2, const float* __restrict__ blin2,
            const float* __restrict__ Wlin3, const float* __restrict__ blin3,
            float* __restrict__ out, int out_size)
{
    extern __shared__ char smraw[];
    SMem* sm = (SMem*)smraw;
    int b = blockIdx.x, tid = threadIdx.x;
    int w = tid >> 5, lane = tid & 31;
    int base = b * N;

    // ---- stage conv/pool weights early ----
    for (int i = tid; i < H*H; i += NTHR) {
        int k = i >> 5, l = i & 31;
        sm->wr[l*WSTR + k] = Wrel[i];
        sm->wo[l*WSTR + k] = Wroot[i];
    }
    for (int i = tid; i < H*K; i += NTHR) {
        int k = i >> 4, l = i & 15;
        sm->wp[l*WSTR + k] = Wpool[i];
    }
    if (tid < H) sm->br[tid] = brel[tid];
    if (tid < K) sm->bp[tid] = bpool[tid];
    if (tid < N) sm->cnt[tid] = 0;

    // ================= fused lin1: h1 = x[b] @ W1 + b1 (FFMA2 tile) ==========
    {
        float* ws = sm->s;                 // overlay
        float* xs = (float*)sm->idx;       // overlay
        for (int i = tid; i < FIN*H; i += NTHR) ws[i] = Wlin1[i];

        int c0 = (tid & 7) * 4;
        int r0 = (tid >> 3) * 4;
        int lr = tid >> 2;
        int q  = tid & 3;

        float bsv[4];
#pragma unroll
        for (int c = 0; c < 4; c++) bsv[c] = blin1[c0 + c];

        const float* xg = x + (size_t)base * FIN;
        float4 nx[2];
#pragma unroll
        for (int p = 0; p < 2; p++)
            nx[p] = *(const float4*)&xg[(size_t)(lr + p*128)*FIN + q*4];

        unsigned long long acc[2][4];
#pragma unroll
        for (int pr = 0; pr < 2; pr++)
#pragma unroll
            for (int c = 0; c < 4; c++)
                acc[pr][c] = pk2(bsv[c], bsv[c]);

        for (int kt = 0; kt < 8; kt++) {
            __syncthreads();
#pragma unroll
            for (int p = 0; p < 2; p++) {
                int row = lr + p*128;
                xs[(q*4+0)*RS + row] = nx[p].x;
                xs[(q*4+1)*RS + row] = nx[p].y;
                xs[(q*4+2)*RS + row] = nx[p].z;
                xs[(q*4+3)*RS + row] = nx[p].w;
            }
            __syncthreads();
            if (kt < 7) {
#pragma unroll
                for (int p = 0; p < 2; p++)
                    nx[p] = *(const float4*)&xg[(size_t)(lr + p*128)*FIN + (kt+1)*16 + q*4];
            }
#pragma unroll
            for (int k = 0; k < 16; k++) {
                float4 wv = *(const float4*)&ws[(kt*16 + k)*H + c0];
                float4 xa = *(const float4*)&xs[k*RS + r0];
                unsigned long long xp[2], wp2[4];
                xp[0] = pk2(xa.x, xa.y); xp[1] = pk2(xa.z, xa.w);
                wp2[0] = pk2(wv.x, wv.x); wp2[1] = pk2(wv.y, wv.y);
                wp2[2] = pk2(wv.z, wv.z); wp2[3] = pk2(wv.w, wv.w);
#pragma unroll
                for (int pr = 0; pr < 2; pr++) {
                    fma2(acc[pr][0], xp[pr], wp2[0]);
                    fma2(acc[pr][1], xp[pr], wp2[1]);
                    fma2(acc[pr][2], xp[pr], wp2[2]);
                    fma2(acc[pr][3], xp[pr], wp2[3]);
                }
            }
        }
#pragma unroll
        for (int pr = 0; pr < 2; pr++) {
            float lo[4], hi[4];
#pragma unroll
            for (int c = 0; c < 4; c++) upk2(lo[c], hi[c], acc[pr][c]);
            int gr = r0 + 2*pr;
            *(float4*)&sm->h1[gr*H + c0]     = make_float4(lo[0], lo[1], lo[2], lo[3]);
            *(float4*)&sm->h1[(gr+1)*H + c0] = make_float4(hi[0], hi[1], hi[2], hi[3]);
        }
    }
    __syncthreads();

    // ---- sort edges by src ----
    const int* srcg = ei + b*E_PER;
    const int* dstg = ei + ET + b*E_PER;
#pragma unroll
    for (int i = 0; i < E_PER/NTHR; i++)
        atomicAdd(&sm->cnt[srcg[tid + i*NTHR] - base], 1);
    __syncthreads();
    int d0 = 0;
    if (tid < N) { d0 = sm->cnt[tid]; sm->start[tid] = d0; }
    __syncthreads();
    for (int off = 1; off < N; off <<= 1) {
        int v = 0;
        if (tid < N && tid >= off) v = sm->start[tid - off];
        __syncthreads();
        if (tid < N) sm->start[tid] += v;
        __syncthreads();
    }
    if (tid < N) {
        int st0 = sm->start[tid] - d0;
        sm->deg[tid] = d0;
        sm->start[tid] = st0;
        sm->cnt[tid] = st0;
    }
    __syncthreads();
#pragma unroll
    for (int i = 0; i < E_PER/NTHR; i++) {
        int u = srcg[tid + i*NTHR] - base;
        int p = atomicAdd(&sm->cnt[u], 1);
        sm->idx[p] = (unsigned short)(dstg[tid + i*NTHR] - base);
    }
    __syncthreads();

    // ---- Phase A: 4-node batches — gather, shared-weight transform, pool ----
    float px_reg[16];
#pragma unroll
    for (int k = 0; k < 16; k++) px_reg[k] = 0.f;

    {
        int grp = lane >> 3, q8 = lane & 7;
        const float4* h1r = (const float4*)sm->h1;
        float* aggb = sm->wk + w*128;          // 4 nodes x 32
        float* hcb  = sm->wk + 2048 + w*128;   // 4 nodes x 32

        for (int u0 = w*NPW; u0 < w*NPW + NPW; u0 += 4) {
            // gather 4 nodes (sequential, MLP=2 each)
#pragma unroll
            for (int g = 0; g < 4; g++) {
                int u = u0 + g;
                int d  = sm->deg[u];
                int st = sm->start[u];
                float4 a0 = make_float4(0.f, 0.f, 0.f, 0.f);
                float4 a1 = make_float4(0.f, 0.f, 0.f, 0.f);
                int i = grp;
                for (; i + 4 < d; i += 8) {
                    int v0 = sm->idx[st + i];
                    int v1 = sm->idx[st + i + 4];
                    float4 r0 = h1r[v0*8 + q8];
                    float4 r1 = h1r[v1*8 + q8];
                    a0.x += r0.x; a0.y += r0.y; a0.z += r0.z; a0.w += r0.w;
                    a1.x += r1.x; a1.y += r1.y; a1.z += r1.z; a1.w += r1.w;
                }
                if (i < d) {
                    int v0 = sm->idx[st + i];
                    float4 r0 = h1r[v0*8 + q8];
                    a0.x += r0.x; a0.y += r0.y; a0.z += r0.z; a0.w += r0.w;
                }
                float4 a = make_float4(a0.x + a1.x, a0.y + a1.y, a0.z + a1.z, a0.w + a1.w);
                a.x += __shfl_xor_sync(FULL, a.x, 8); a.x += __shfl_xor_sync(FULL, a.x, 16);
                a.y += __shfl_xor_sync(FULL, a.y, 8); a.y += __shfl_xor_sync(FULL, a.y, 16);
                a.z += __shfl_xor_sync(FULL, a.z, 8); a.z += __shfl_xor_sync(FULL, a.z, 16);
                a.w += __shfl_xor_sync(FULL, a.w, 8); a.w += __shfl_xor_sync(FULL, a.w, 16);
                if (lane < 8) *(float4*)&aggb[g*32 + lane*4] = a;
            }
            __syncwarp();

            // transform: one weight load serves 4 nodes
            float o[4];
#pragma unroll
            for (int g = 0; g < 4; g++) o[g] = sm->br[lane];
#pragma unroll
            for (int c = 0; c < 8; c++) {
                float4 wrv = *(const float4*)&sm->wr[lane*WSTR + 4*c];
                float4 wov = *(const float4*)&sm->wo[lane*WSTR + 4*c];
#pragma unroll
                for (int g = 0; g < 4; g++) {
                    float4 av = *(const float4*)&aggb[g*32 + 4*c];
                    float4 hv = *(const float4*)&sm->h1[(u0+g)*32 + 4*c];
                    o[g] += av.x*wrv.x + hv.x*wov.x;
                    o[g] += av.y*wrv.y + hv.y*wov.y;
                    o[g] += av.z*wrv.z + hv.z*wov.z;
                    o[g] += av.w*wrv.w + hv.w*wov.w;
                }
            }
#pragma unroll
            for (int g = 0; g < 4; g++) hcb[g*32 + lane] = o[g];
            __syncwarp();

            // pool logits: wp hoisted over the 4-node batch
            int lk = lane & 15;
            float sl[4];
#pragma unroll
            for (int g = 0; g < 4; g++) sl[g] = sm->bp[lk];
#pragma unroll
            for (int c = 0; c < 8; c++) {
                float4 wpv = *(const float4*)&sm->wp[lk*WSTR + 4*c];
#pragma unroll
                for (int g = 0; g < 4; g++) {
                    float4 hq = *(const float4*)&hcb[g*32 + 4*c];
                    sl[g] += hq.x*wpv.x + hq.y*wpv.y + hq.z*wpv.z + hq.w*wpv.w;
                }
            }
            // softmax + s store + px rank-1, per node
#pragma unroll
            for (int g = 0; g < 4; g++) {
                float m = sl[g];
#pragma unroll
                for (int off = 8; off >= 1; off >>= 1)
                    m = fmaxf(m, __shfl_xor_sync(FULL, m, off, 16));
                float e = expf(sl[g] - m);
                float sum = e;
#pragma unroll
                for (int off = 8; off >= 1; off >>= 1)
                    sum += __shfl_xor_sync(FULL, sum, off, 16);
                float svx = e / sum;
                if (lane < 16) sm->s[(u0+g)*16 + lk] = svx;
#pragma unroll
                for (int k = 0; k < 16; k++) {
                    float sk = __shfl_sync(FULL, svx, k);
                    px_reg[k] += sk * o[g];
                }
            }
        }
    }
    __syncthreads();

    // ---- px reduction across 16 warps (2 rounds of 8 via wk) ----
    for (int round = 0; round < 2; round++) {
        if ((w >> 3) == round) {
#pragma unroll
            for (int k = 0; k < 16; k++)
                sm->wk[(w & 7)*512 + k*32 + lane] = px_reg[k];
        }
        __syncthreads();
        {
            float v = 0.f;
#pragma unroll
            for (int ww = 0; ww < 8; ww++) v += sm->wk[ww*512 + tid];
            if (round == 0) sm->px[tid] = v; else sm->px[tid] += v;
        }
        __syncthreads();
    }

    // ---- Phase B: t = A@s (MLP=2); out_adj = s^T t, ss = s^T s, den ----
    float oa[8], ob[8];
#pragma unroll
    for (int i = 0; i < 8; i++) { oa[i] = 0.f; ob[i] = 0.f; }
    float den_acc = 0.f;
    {
        int grp8 = lane >> 2, q4 = lane & 3;
        int j = lane & 15, kh = lane >> 4;
        const float4* ssr = (const float4*)sm->s;
        for (int u = w*NPW; u < w*NPW + NPW; u++) {
            int d  = sm->deg[u];
            int st = sm->start[u];
            float4 a0 = make_float4(0.f, 0.f, 0.f, 0.f);
            float4 a1 = make_float4(0.f, 0.f, 0.f, 0.f);
            int i = grp8;
            for (; i + 8 < d; i += 16) {
                int v0 = sm->idx[st + i];
                int v1 = sm->idx[st + i + 8];
                float4 r0 = ssr[v0*4 + q4];
                float4 r1 = ssr[v1*4 + q4];
                a0.x += r0.x; a0.y += r0.y; a0.z += r0.z; a0.w += r0.w;
                a1.x += r1.x; a1.y += r1.y; a1.z += r1.z; a1.w += r1.w;
            }
            if (i < d) {
                int v0 = sm->idx[st + i];
                float4 r0 = ssr[v0*4 + q4];
                a0.x += r0.x; a0.y += r0.y; a0.z += r0.z; a0.w += r0.w;
            }
            float4 a = make_float4(a0.x + a1.x, a0.y + a1.y, a0.z + a1.z, a0.w + a1.w);
            a.x += __shfl_xor_sync(FULL, a.x, 4); a.x += __shfl_xor_sync(FULL, a.x, 8); a.x += __shfl_xor_sync(FULL, a.x, 16);
            a.y += __shfl_xor_sync(FULL, a.y, 4); a.y += __shfl_xor_sync(FULL, a.y, 8); a.y += __shfl_xor_sync(FULL, a.y, 16);
            a.z += __shfl_xor_sync(FULL, a.z, 4); a.z += __shfl_xor_sync(FULL, a.z, 8); a.z += __shfl_xor_sync(FULL, a.z, 16);
            a.w += __shfl_xor_sync(FULL, a.w, 4); a.w += __shfl_xor_sync(FULL, a.w, 8); a.w += __shfl_xor_sync(FULL, a.w, 16);
            if (lane < 4) *(float4*)&sm->tbuf[w*16 + lane*4] = a;
            __syncwarp();
            float tj = sm->tbuf[w*16 + j];
            float sj = sm->s[u*16 + j];
            __syncwarp();

            float v2 = sj*sj;
            v2 += __shfl_xor_sync(FULL, v2, 1, 16);
            v2 += __shfl_xor_sync(FULL, v2, 2, 16);
            v2 += __shfl_xor_sync(FULL, v2, 4, 16);
            v2 += __shfl_xor_sync(FULL, v2, 8, 16);
            den_acc += (float)d * v2;

#pragma unroll
            for (int kk = 0; kk < 8; kk++) {
                float su = sm->s[u*16 + kh*8 + kk];
                oa[kk] += su * tj;
                ob[kk] += su * sj;
            }
        }
    }
    __syncthreads();

    // ---- reduce out_adj + ss + den (2 rounds of 8 warps, both at once) ----
    {
        int j = lane & 15, kh = lane >> 4;
        if (lane == 0) sm->red[w] = den_acc;
        for (int round = 0; round < 2; round++) {
            if ((w >> 3) == round) {
#pragma unroll
                for (int kk = 0; kk < 8; kk++) {
                    sm->wk[(w & 7)*256 + (kh*8+kk)*16 + j] = oa[kk];
                    sm->wk[2048 + (w & 7)*256 + (kh*8+kk)*16 + j] = ob[kk];
                }
            }
            __syncthreads();
            if (tid < 256) {
                float v = 0.f, v2 = 0.f;
#pragma unroll
                for (int ww = 0; ww < 8; ww++) {
                    v  += sm->wk[ww*256 + tid];
                    v2 += sm->wk[2048 + ww*256 + tid];
                }
                if (round == 0) { sm->adj[tid] = v; sm->ssm[tid] = v2; }
                else            { sm->adj[tid] += v; sm->ssm[tid] += v2; }
            }
            __syncthreads();
        }
    }

    // ---- losses (CTA partials -> global atomics) ----
    int kq = (tid >> 4) & 15, jq = tid & 15;
    float mincut_part = 0.f;
    if (tid == 0) {
        float den = 0.f;
        for (int i = 0; i < NW; i++) den += sm->red[i];
        float num = 0.f;
        for (int kk = 0; kk < K; kk++) num += sm->adj[kk*K + kk];
        mincut_part = -(num / den);
    }
    float ssv = (tid < 256) ? sm->ssm[tid] : 0.f;
    if (tid < 256) sm->wk[tid] = ssv * ssv;
    __syncthreads();
    for (int off = 128; off > 0; off >>= 1) { if (tid < off) sm->wk[tid] += sm->wk[tid + off]; __syncthreads(); }
    float nrm = sqrtf(sm->wk[0]);
    __syncthreads();
    if (tid < 256) {
        float diff = ssv / nrm - ((kq == jq) ? 0.25f : 0.f);
        sm->wk[tid] = diff * diff;
    }
    __syncthreads();
    for (int off = 128; off > 0; off >>= 1) { if (tid < off) sm->wk[tid] += sm->wk[tid + off]; __syncthreads(); }
    float ortho_part = (tid == 0) ? sqrtf(sm->wk[0]) : 0.f;
    __syncthreads();

    // ---- normalize out_adj ----
    if (tid < 256) {
        float av = (kq == jq) ? 0.f : sm->adj[tid];
        sm->adj[tid] = av;
    }
    __syncthreads();
    if (tid < K) {
        float rs = 0.f;
        for (int jj = 0; jj < K; jj++) rs += sm->adj[tid*K + jj];
        sm->sd[tid] = sqrtf(rs) + EPSF;
    }
    __syncthreads();
    if (tid < 256) sm->adj[tid] = sm->adj[tid] / (sm->sd[kq] * sm->sd[jq]);
    __syncthreads();

    // ---- conv2 on pooled features (one (kc,h) per thread) ----
    {
        int h = tid & 31, kc = tid >> 5;   // kc 0..15
        float m1 = 0.f;
#pragma unroll
        for (int jj = 0; jj < K; jj++) m1 += sm->adj[kc*K + jj] * sm->px[jj*H + h];
        sm->wk[kc*H + h] = m1;
    }
    __syncthreads();
    {
        int h = tid & 31, kc = tid >> 5;
        float acc = brel2[h];
        for (int c = 0; c < H; c++)
            acc += sm->wk[kc*H + c] * Wrel2[c*H + h] + sm->px[kc*H + c] * Wroot2[c*H + h];
        sm->wk[512 + kc*H + h] = acc;
    }
    __syncthreads();

    // ---- readout + MLP + log_softmax ----
    if (tid < H) {
        float r = 0.f;
#pragma unroll
        for (int kk = 0; kk < K; kk++) r += sm->wk[512 + kk*H + tid];
        sm->sr[tid] = r;
    }
    __syncthreads();
    if (tid < H) {
        float a2 = blin2[tid];
        for (int c = 0; c < H; c++) a2 += sm->sr[c] * Wlin2[c*H + tid];
        sm->sh3[tid] = fmaxf(a2, 0.f);
    }
    __syncthreads();
    if (tid < FOUT) {
        float a3 = blin3[tid];
        for (int c = 0; c < H; c++) a3 += sm->sh3[c] * Wlin3[c*FOUT + tid];
        sm->so[tid] = a3;
    }
    __syncthreads();
    if (tid == 0) {
        float m = sm->so[0];
        for (int i = 1; i < FOUT; i++) m = fmaxf(m, sm->so[i]);
        float s = 0.f;
        for (int i = 0; i < FOUT; i++) s += expf(sm->so[i] - m);
        float lse = m + logf(s);
        for (int i = 0; i < FOUT; i++) out[b*FOUT + i] = sm->so[i] - lse;

        // global loss reduction; last CTA writes + resets (graph-replay safe)
        atomicAdd(&g_acc[0], mincut_part * (1.f/(float)B));
        atomicAdd(&g_acc[1], ortho_part  * (1.f/(float)B));
        __threadfence();
        int old = atomicAdd(&g_ctr, 1);
        if (old == B - 1) {
            __threadfence();
            float l0 = g_acc[0], l1 = g_acc[1];
            if (out_size > B*FOUT)     out[B*FOUT]     = l0;
            if (out_size > B*FOUT + 1) out[B*FOUT + 1] = l1;
            g_acc[0] = 0.f; g_acc[1] = 0.f;
            g_ctr = 0;
            __threadfence();
        }
    }
}

// ---------------- launch ----------------
extern "C" void kernel_launch(void* const* d_in, const int* in_sizes, int n_in,
                              void* d_out, int out_size) {
    const float* x     = (const float*)d_in[0];
    const int*   ei    = (const int*)d_in[1];
    const float* Wlin1 = (const float*)d_in[3];
    const float* blin1 = (const float*)d_in[4];
    const float* Wrel1 = (const float*)d_in[5];
    const float* brel1 = (const float*)d_in[6];
    const float* Wroot1= (const float*)d_in[7];
    const float* Wpool = (const float*)d_in[8];
    const float* bpool = (const float*)d_in[9];
    const float* Wrel2 = (const float*)d_in[10];
    const float* brel2 = (const float*)d_in[11];
    const float* Wroot2= (const float*)d_in[12];
    const float* Wlin2 = (const float*)d_in[13];
    const float* blin2 = (const float*)d_in[14];
    const float* Wlin3 = (const float*)d_in[15];
    const float* blin3 = (const float*)d_in[16];
    float* out = (float*)d_out;

    cudaFuncSetAttribute(k_mega, cudaFuncAttributeMaxDynamicSharedMemorySize,
                         (int)sizeof(SMem));

    k_mega<<<B, NTHR, sizeof(SMem)>>>(x, ei, Wlin1, blin1,
                                      Wrel1, brel1, Wroot1, Wpool, bpool,
                                      Wrel2, brel2, Wroot2,
                                      Wlin2, blin2, Wlin3, blin3, out, out_size);
}

// round 12
// speedup vs baseline: 1.2065x; 1.0016x over previous
#include <cuda_runtime.h>

#define B 512
#define N 256
#define E_PER 8192
#define NT (B*N)
#define ET (B*E_PER)
#define FIN 128
#define H 32
#define K 16
#define FOUT 10
#define EPSF 1e-15f
#define FULL 0xffffffffu
#define WSTR 36         // padded transposed-weight stride
#define RS   260        // xs transpose stride
#define NTHR 512
#define NW   16         // warps per CTA
#define NPW  16         // nodes per warp
#define PH1  36         // padded h1 row stride (floats)
#define PH1Q 9          // h1 row stride in float4
#define PS   20         // padded s row stride (floats)
#define PSQ  5          // s row stride in float4

// ---------------- globals ----------------
__device__ float g_acc[2] = {0.f, 0.f};
__device__ int   g_ctr = 0;

// ---------------- f32x2 helpers ----------------
__device__ __forceinline__ unsigned long long pk2(float lo, float hi) {
    unsigned long long r;
    asm("mov.b64 %0, {%1,%2};" : "=l"(r)
        : "r"(__float_as_uint(lo)), "r"(__float_as_uint(hi)));
    return r;
}
__device__ __forceinline__ void fma2(unsigned long long& d,
                                     unsigned long long a, unsigned long long b) {
    asm("fma.rn.f32x2 %0, %1, %2, %0;" : "+l"(d) : "l"(a), "l"(b));
}
__device__ __forceinline__ void upk2(float& lo, float& hi, unsigned long long v) {
    unsigned int a, b2;
    asm("mov.b64 {%0,%1}, %2;" : "=r"(a), "=r"(b2) : "l"(v));
    lo = __uint_as_float(a); hi = __uint_as_float(b2);
}

// ---------------- mega-kernel shared layout ----------------
struct SMem {
    float h1[N*PH1];          // 36864 B (padded rows, conflict-free gather)
    float s[N*PS];            // 20480 B (padded; overlaid by ws[FIN*H] in lin1)
    float wk[4096];           // 16384 B: aggb/hcb strips, reductions, conv2
    float wr[H*WSTR];
    float wo[H*WSTR];
    float wp[K*WSTR];
    float br[H];
    float bp[K];
    float px[K*H];
    float adj[K*K];
    float ssm[K*K];
    float red[32];
    float tbuf[NW*16];
    float sd[K];
    float sr[H];
    float sh3[H];
    float so[FOUT];
    alignas(16) unsigned short idx[E_PER];  // overlaid by xs[16*RS] during lin1
    int deg[N];               // xs overlay spills 256B into deg (rewritten later)
    int start[N];
    int cnt[N];
};

// ---------------- mega: entire network, one CTA per graph, 512 threads ------
__global__ __launch_bounds__(NTHR, 2)
void k_mega(const float* __restrict__ x,
            const int* __restrict__ ei,
            const float* __restrict__ Wlin1, const float* __restrict__ blin1,
            const float* __restrict__ Wrel,  const float* __restrict__ brel,
            const float* __restrict__ Wroot, const float* __restrict__ Wpool,
            const float* __restrict__ bpool,
            const float* __restrict__ Wrel2, const float* __restrict__ brel2,
            const float* __restrict__ Wroot2,
            const float* __restrict__ Wlin2, const float* __restrict__ blin2,
            const float* __restrict__ Wlin3, const float* __restrict__ blin3,
            float* __restrict__ out, int out_size)
{
    extern __shared__ char smraw[];
    SMem* sm = (SMem*)smraw;
    int b = blockIdx.x, tid = threadIdx.x;
    int w = tid >> 5, lane = tid & 31;
    int base = b * N;

    // ---- stage conv/pool weights early ----
    for (int i = tid; i < H*H; i += NTHR) {
        int k = i >> 5, l = i & 31;
        sm->wr[l*WSTR + k] = Wrel[i];
        sm->wo[l*WSTR + k] = Wroot[i];
    }
    for (int i = tid; i < H*K; i += NTHR) {
        int k = i >> 4, l = i & 15;
        sm->wp[l*WSTR + k] = Wpool[i];
    }
    if (tid < H) sm->br[tid] = brel[tid];
    if (tid < K) sm->bp[tid] = bpool[tid];
    if (tid < N) sm->cnt[tid] = 0;

    // ================= fused lin1: h1 = x[b] @ W1 + b1 (FFMA2 tile) ==========
    {
        float* ws = sm->s;                 // overlay (needs 16384B; s is 20480B)
        float* xs = (float*)sm->idx;       // overlay
        for (int i = tid; i < FIN*H; i += NTHR) ws[i] = Wlin1[i];

        int c0 = (tid & 7) * 4;
        int r0 = (tid >> 3) * 4;
        int lr = tid >> 2;
        int q  = tid & 3;

        float bsv[4];
#pragma unroll
        for (int c = 0; c < 4; c++) bsv[c] = blin1[c0 + c];

        const float* xg = x + (size_t)base * FIN;
        float4 nx[2];
#pragma unroll
        for (int p = 0; p < 2; p++)
            nx[p] = *(const float4*)&xg[(size_t)(lr + p*128)*FIN + q*4];

        unsigned long long acc[2][4];
#pragma unroll
        for (int pr = 0; pr < 2; pr++)
#pragma unroll
            for (int c = 0; c < 4; c++)
                acc[pr][c] = pk2(bsv[c], bsv[c]);

        for (int kt = 0; kt < 8; kt++) {
            __syncthreads();
#pragma unroll
            for (int p = 0; p < 2; p++) {
                int row = lr + p*128;
                xs[(q*4+0)*RS + row] = nx[p].x;
                xs[(q*4+1)*RS + row] = nx[p].y;
                xs[(q*4+2)*RS + row] = nx[p].z;
                xs[(q*4+3)*RS + row] = nx[p].w;
            }
            __syncthreads();
            if (kt < 7) {
#pragma unroll
                for (int p = 0; p < 2; p++)
                    nx[p] = *(const float4*)&xg[(size_t)(lr + p*128)*FIN + (kt+1)*16 + q*4];
            }
#pragma unroll
            for (int k = 0; k < 16; k++) {
                float4 wv = *(const float4*)&ws[(kt*16 + k)*H + c0];
                float4 xa = *(const float4*)&xs[k*RS + r0];
                unsigned long long xp[2], wp2[4];
                xp[0] = pk2(xa.x, xa.y); xp[1] = pk2(xa.z, xa.w);
                wp2[0] = pk2(wv.x, wv.x); wp2[1] = pk2(wv.y, wv.y);
                wp2[2] = pk2(wv.z, wv.z); wp2[3] = pk2(wv.w, wv.w);
#pragma unroll
                for (int pr = 0; pr < 2; pr++) {
                    fma2(acc[pr][0], xp[pr], wp2[0]);
                    fma2(acc[pr][1], xp[pr], wp2[1]);
                    fma2(acc[pr][2], xp[pr], wp2[2]);
                    fma2(acc[pr][3], xp[pr], wp2[3]);
                }
            }
        }
#pragma unroll
        for (int pr = 0; pr < 2; pr++) {
            float lo[4], hi[4];
#pragma unroll
            for (int c = 0; c < 4; c++) upk2(lo[c], hi[c], acc[pr][c]);
            int gr = r0 + 2*pr;
            *(float4*)&sm->h1[gr*PH1 + c0]     = make_float4(lo[0], lo[1], lo[2], lo[3]);
            *(float4*)&sm->h1[(gr+1)*PH1 + c0] = make_float4(hi[0], hi[1], hi[2], hi[3]);
        }
    }
    __syncthreads();

    // ---- sort edges by src ----
    const int* srcg = ei + b*E_PER;
    const int* dstg = ei + ET + b*E_PER;
#pragma unroll
    for (int i = 0; i < E_PER/NTHR; i++)
        atomicAdd(&sm->cnt[srcg[tid + i*NTHR] - base], 1);
    __syncthreads();
    int d0 = 0;
    if (tid < N) { d0 = sm->cnt[tid]; sm->start[tid] = d0; }
    __syncthreads();
    for (int off = 1; off < N; off <<= 1) {
        int v = 0;
        if (tid < N && tid >= off) v = sm->start[tid - off];
        __syncthreads();
        if (tid < N) sm->start[tid] += v;
        __syncthreads();
    }
    if (tid < N) {
        int st0 = sm->start[tid] - d0;
        sm->deg[tid] = d0;
        sm->start[tid] = st0;
        sm->cnt[tid] = st0;
    }
    __syncthreads();
#pragma unroll
    for (int i = 0; i < E_PER/NTHR; i++) {
        int u = srcg[tid + i*NTHR] - base;
        int p = atomicAdd(&sm->cnt[u], 1);
        sm->idx[p] = (unsigned short)(dstg[tid + i*NTHR] - base);
    }
    __syncthreads();

    // ---- Phase A: 4-node batches — gather, shared-weight transform, pool ----
    float px_reg[16];
#pragma unroll
    for (int k = 0; k < 16; k++) px_reg[k] = 0.f;

    {
        int grp = lane >> 3, q8 = lane & 7;
        const float4* h1r = (const float4*)sm->h1;
        float* aggb = sm->wk + w*128;          // 4 nodes x 32
        float* hcb  = sm->wk + 2048 + w*128;   // 4 nodes x 32

        for (int u0 = w*NPW; u0 < w*NPW + NPW; u0 += 4) {
            // gather 4 nodes (sequential, MLP=2 each)
#pragma unroll
            for (int g = 0; g < 4; g++) {
                int u = u0 + g;
                int d  = sm->deg[u];
                int st = sm->start[u];
                float4 a0 = make_float4(0.f, 0.f, 0.f, 0.f);
                float4 a1 = make_float4(0.f, 0.f, 0.f, 0.f);
                int i = grp;
                for (; i + 4 < d; i += 8) {
                    int v0 = sm->idx[st + i];
                    int v1 = sm->idx[st + i + 4];
                    float4 r0 = h1r[v0*PH1Q + q8];
                    float4 r1 = h1r[v1*PH1Q + q8];
                    a0.x += r0.x; a0.y += r0.y; a0.z += r0.z; a0.w += r0.w;
                    a1.x += r1.x; a1.y += r1.y; a1.z += r1.z; a1.w += r1.w;
                }
                if (i < d) {
                    int v0 = sm->idx[st + i];
                    float4 r0 = h1r[v0*PH1Q + q8];
                    a0.x += r0.x; a0.y += r0.y; a0.z += r0.z; a0.w += r0.w;
                }
                float4 a = make_float4(a0.x + a1.x, a0.y + a1.y, a0.z + a1.z, a0.w + a1.w);
                a.x += __shfl_xor_sync(FULL, a.x, 8); a.x += __shfl_xor_sync(FULL, a.x, 16);
                a.y += __shfl_xor_sync(FULL, a.y, 8); a.y += __shfl_xor_sync(FULL, a.y, 16);
                a.z += __shfl_xor_sync(FULL, a.z, 8); a.z += __shfl_xor_sync(FULL, a.z, 16);
                a.w += __shfl_xor_sync(FULL, a.w, 8); a.w += __shfl_xor_sync(FULL, a.w, 16);
                if (lane < 8) *(float4*)&aggb[g*32 + lane*4] = a;
            }
            __syncwarp();

            // transform: one weight load serves 4 nodes
            float o[4];
#pragma unroll
            for (int g = 0; g < 4; g++) o[g] = sm->br[lane];
#pragma unroll
            for (int c = 0; c < 8; c++) {
                float4 wrv = *(const float4*)&sm->wr[lane*WSTR + 4*c];
                float4 wov = *(const float4*)&sm->wo[lane*WSTR + 4*c];
#pragma unroll
                for (int g = 0; g < 4; g++) {
                    float4 av = *(const float4*)&aggb[g*32 + 4*c];
                    float4 hv = *(const float4*)&sm->h1[(u0+g)*PH1 + 4*c];
                    o[g] += av.x*wrv.x + hv.x*wov.x;
                    o[g] += av.y*wrv.y + hv.y*wov.y;
                    o[g] += av.z*wrv.z + hv.z*wov.z;
                    o[g] += av.w*wrv.w + hv.w*wov.w;
                }
            }
#pragma unroll
            for (int g = 0; g < 4; g++) hcb[g*32 + lane] = o[g];
            __syncwarp();

            // pool logits: wp hoisted over the 4-node batch
            int lk = lane & 15;
            float sl[4];
#pragma unroll
            for (int g = 0; g < 4; g++) sl[g] = sm->bp[lk];
#pragma unroll
            for (int c = 0; c < 8; c++) {
                float4 wpv = *(const float4*)&sm->wp[lk*WSTR + 4*c];
#pragma unroll
                for (int g = 0; g < 4; g++) {
                    float4 hq = *(const float4*)&hcb[g*32 + 4*c];
                    sl[g] += hq.x*wpv.x + hq.y*wpv.y + hq.z*wpv.z + hq.w*wpv.w;
                }
            }
            // softmax + s store + px rank-1, per node
#pragma unroll
            for (int g = 0; g < 4; g++) {
                float m = sl[g];
#pragma unroll
                for (int off = 8; off >= 1; off >>= 1)
                    m = fmaxf(m, __shfl_xor_sync(FULL, m, off, 16));
                float e = expf(sl[g] - m);
                float sum = e;
#pragma unroll
                for (int off = 8; off >= 1; off >>= 1)
                    sum += __shfl_xor_sync(FULL, sum, off, 16);
                float svx = e / sum;
                if (lane < 16) sm->s[(u0+g)*PS + lk] = svx;
#pragma unroll
                for (int k = 0; k < 16; k++) {
                    float sk = __shfl_sync(FULL, svx, k);
                    px_reg[k] += sk * o[g];
                }
            }
        }
    }
    __syncthreads();

    // ---- px reduction across 16 warps (2 rounds of 8 via wk) ----
    for (int round = 0; round < 2; round++) {
        if ((w >> 3) == round) {
#pragma unroll
            for (int k = 0; k < 16; k++)
                sm->wk[(w & 7)*512 + k*32 + lane] = px_reg[k];
        }
        __syncthreads();
        {
            float v = 0.f;
#pragma unroll
            for (int ww = 0; ww < 8; ww++) v += sm->wk[ww*512 + tid];
            if (round == 0) sm->px[tid] = v; else sm->px[tid] += v;
        }
        __syncthreads();
    }

    // ---- Phase B: t = A@s (MLP=2); out_adj = s^T t, ss = s^T s, den ----
    float oa[8], ob[8];
#pragma unroll
    for (int i = 0; i < 8; i++) { oa[i] = 0.f; ob[i] = 0.f; }
    float den_acc = 0.f;
    {
        int grp8 = lane >> 2, q4 = lane & 3;
        int j = lane & 15, kh = lane >> 4;
        const float4* ssr = (const float4*)sm->s;
        for (int u = w*NPW; u < w*NPW + NPW; u++) {
            int d  = sm->deg[u];
            int st = sm->start[u];
            float4 a0 = make_float4(0.f, 0.f, 0.f, 0.f);
            float4 a1 = make_float4(0.f, 0.f, 0.f, 0.f);
            int i = grp8;
            for (; i + 8 < d; i += 16) {
                int v0 = sm->idx[st + i];
                int v1 = sm->idx[st + i + 8];
                float4 r0 = ssr[v0*PSQ + q4];
                float4 r1 = ssr[v1*PSQ + q4];
                a0.x += r0.x; a0.y += r0.y; a0.z += r0.z; a0.w += r0.w;
                a1.x += r1.x; a1.y += r1.y; a1.z += r1.z; a1.w += r1.w;
            }
            if (i < d) {
                int v0 = sm->idx[st + i];
                float4 r0 = ssr[v0*PSQ + q4];
                a0.x += r0.x; a0.y += r0.y; a0.z += r0.z; a0.w += r0.w;
            }
            float4 a = make_float4(a0.x + a1.x, a0.y + a1.y, a0.z + a1.z, a0.w + a1.w);
            a.x += __shfl_xor_sync(FULL, a.x, 4); a.x += __shfl_xor_sync(FULL, a.x, 8); a.x += __shfl_xor_sync(FULL, a.x, 16);
            a.y += __shfl_xor_sync(FULL, a.y, 4); a.y += __shfl_xor_sync(FULL, a.y, 8); a.y += __shfl_xor_sync(FULL, a.y, 16);
            a.z += __shfl_xor_sync(FULL, a.z, 4); a.z += __shfl_xor_sync(FULL, a.z, 8); a.z += __shfl_xor_sync(FULL, a.z, 16);
            a.w += __shfl_xor_sync(FULL, a.w, 4); a.w += __shfl_xor_sync(FULL, a.w, 8); a.w += __shfl_xor_sync(FULL, a.w, 16);
            if (lane < 4) *(float4*)&sm->tbuf[w*16 + lane*4] = a;
            __syncwarp();
            float tj = sm->tbuf[w*16 + j];
            float sj = sm->s[u*PS + j];
            __syncwarp();

            float v2 = sj*sj;
            v2 += __shfl_xor_sync(FULL, v2, 1, 16);
            v2 += __shfl_xor_sync(FULL, v2, 2, 16);
            v2 += __shfl_xor_sync(FULL, v2, 4, 16);
            v2 += __shfl_xor_sync(FULL, v2, 8, 16);
            den_acc += (float)d * v2;

#pragma unroll
            for (int kk = 0; kk < 8; kk++) {
                float su = sm->s[u*PS + kh*8 + kk];
                oa[kk] += su * tj;
                ob[kk] += su * sj;
            }
        }
    }
    __syncthreads();

    // ---- reduce out_adj + ss + den (2 rounds of 8 warps, both at once) ----
    {
        int j = lane & 15, kh = lane >> 4;
        if (lane == 0) sm->red[w] = den_acc;
        for (int round = 0; round < 2; round++) {
            if ((w >> 3) == round) {
#pragma unroll
                for (int kk = 0; kk < 8; kk++) {
                    sm->wk[(w & 7)*256 + (kh*8+kk)*16 + j] = oa[kk];
                    sm->wk[2048 + (w & 7)*256 + (kh*8+kk)*16 + j] = ob[kk];
                }
            }
            __syncthreads();
            if (tid < 256) {
                float v = 0.f, v2 = 0.f;
#pragma unroll
                for (int ww = 0; ww < 8; ww++) {
                    v  += sm->wk[ww*256 + tid];
                    v2 += sm->wk[2048 + ww*256 + tid];
                }
                if (round == 0) { sm->adj[tid] = v; sm->ssm[tid] = v2; }
                else            { sm->adj[tid] += v; sm->ssm[tid] += v2; }
            }
            __syncthreads();
        }
    }

    // ---- losses (CTA partials -> global atomics) ----
    int kq = (tid >> 4) & 15, jq = tid & 15;
    float mincut_part = 0.f;
    if (tid == 0) {
        float den = 0.f;
        for (int i = 0; i < NW; i++) den += sm->red[i];
        float num = 0.f;
        for (int kk = 0; kk < K; kk++) num += sm->adj[kk*K + kk];
        mincut_part = -(num / den);
    }
    float ssv = (tid < 256) ? sm->ssm[tid] : 0.f;
    if (tid < 256) sm->wk[tid] = ssv * ssv;
    __syncthreads();
    for (int off = 128; off > 0; off >>= 1) { if (tid < off) sm->wk[tid] += sm->wk[tid + off]; __syncthreads(); }
    float nrm = sqrtf(sm->wk[0]);
    __syncthreads();
    if (tid < 256) {
        float diff = ssv / nrm - ((kq == jq) ? 0.25f : 0.f);
        sm->wk[tid] = diff * diff;
    }
    __syncthreads();
    for (int off = 128; off > 0; off >>= 1) { if (tid < off) sm->wk[tid] += sm->wk[tid + off]; __syncthreads(); }
    float ortho_part = (tid == 0) ? sqrtf(sm->wk[0]) : 0.f;
    __syncthreads();

    // ---- normalize out_adj ----
    if (tid < 256) {
        float av = (kq == jq) ? 0.f : sm->adj[tid];
        sm->adj[tid] = av;
    }
    __syncthreads();
    if (tid < K) {
        float rs = 0.f;
        for (int jj = 0; jj < K; jj++) rs += sm->adj[tid*K + jj];
        sm->sd[tid] = sqrtf(rs) + EPSF;
    }
    __syncthreads();
    if (tid < 256) sm->adj[tid] = sm->adj[tid] / (sm->sd[kq] * sm->sd[jq]);
    __syncthreads();

    // ---- conv2 on pooled features (one (kc,h) per thread) ----
    {
        int h = tid & 31, kc = tid >> 5;   // kc 0..15
        float m1 = 0.f;
#pragma unroll
        for (int jj = 0; jj < K; jj++) m1 += sm->adj[kc*K + jj] * sm->px[jj*H + h];
        sm->wk[kc*H + h] = m1;
    }
    __syncthreads();
    {
        int h = tid & 31, kc = tid >> 5;
        float acc = brel2[h];
        for (int c = 0; c < H; c++)
            acc += sm->wk[kc*H + c] * Wrel2[c*H + h] + sm->px[kc*H + c] * Wroot2[c*H + h];
        sm->wk[512 + kc*H + h] = acc;
    }
    __syncthreads();

    // ---- readout + MLP + log_softmax ----
    if (tid < H) {
        float r = 0.f;
#pragma unroll
        for (int kk = 0; kk < K; kk++) r += sm->wk[512 + kk*H + tid];
        sm->sr[tid] = r;
    }
    __syncthreads();
    if (tid < H) {
        float a2 = blin2[tid];
        for (int c = 0; c < H; c++) a2 += sm->sr[c] * Wlin2[c*H + tid];
        sm->sh3[tid] = fmaxf(a2, 0.f);
    }
    __syncthreads();
    if (tid < FOUT) {
        float a3 = blin3[tid];
        for (int c = 0; c < H; c++) a3 += sm->sh3[c] * Wlin3[c*FOUT + tid];
        sm->so[tid] = a3;
    }
    __syncthreads();
    if (tid == 0) {
        float m = sm->so[0];
        for (int i = 1; i < FOUT; i++) m = fmaxf(m, sm->so[i]);
        float s = 0.f;
        for (int i = 0; i < FOUT; i++) s += expf(sm->so[i] - m);
        float lse = m + logf(s);
        for (int i = 0; i < FOUT; i++) out[b*FOUT + i] = sm->so[i] - lse;

        // global loss reduction; last CTA writes + resets (graph-replay safe)
        atomicAdd(&g_acc[0], mincut_part * (1.f/(float)B));
        atomicAdd(&g_acc[1], ortho_part  * (1.f/(float)B));
        __threadfence();
        int old = atomicAdd(&g_ctr, 1);
        if (old == B - 1) {
            __threadfence();
            float l0 = g_acc[0], l1 = g_acc[1];
            if (out_size > B*FOUT)     out[B*FOUT]     = l0;
            if (out_size > B*FOUT + 1) out[B*FOUT + 1] = l1;
            g_acc[0] = 0.f; g_acc[1] = 0.f;
            g_ctr = 0;
            __threadfence();
        }
    }
}

// ---------------- launch ----------------
extern "C" void kernel_launch(void* const* d_in, const int* in_sizes, int n_in,
                              void* d_out, int out_size) {
    const float* x     = (const float*)d_in[0];
    const int*   ei    = (const int*)d_in[1];
    const float* Wlin1 = (const float*)d_in[3];
    const float* blin1 = (const float*)d_in[4];
    const float* Wrel1 = (const float*)d_in[5];
    const float* brel1 = (const float*)d_in[6];
    const float* Wroot1= (const float*)d_in[7];
    const float* Wpool = (const float*)d_in[8];
    const float* bpool = (const float*)d_in[9];
    const float* Wrel2 = (const float*)d_in[10];
    const float* brel2 = (const float*)d_in[11];
    const float* Wroot2= (const float*)d_in[12];
    const float* Wlin2 = (const float*)d_in[13];
    const float* blin2 = (const float*)d_in[14];
    const float* Wlin3 = (const float*)d_in[15];
    const float* blin3 = (const float*)d_in[16];
    float* out = (float*)d_out;

    cudaFuncSetAttribute(k_mega, cudaFuncAttributeMaxDynamicSharedMemorySize,
                         (int)sizeof(SMem));

    k_mega<<<B, NTHR, sizeof(SMem)>>>(x, ei, Wlin1, blin1,
                                      Wrel1, brel1, Wroot1, Wpool, bpool,
                                      Wrel2, brel2, Wroot2,
                                      Wlin2, blin2, Wlin3, blin3, out, out_size);
}

// round 13
// speedup vs baseline: 1.2212x; 1.0122x over previous
#include <cuda_runtime.h>

#define B 512
#define N 256
#define E_PER 8192
#define NT (B*N)
#define ET (B*E_PER)
#define FIN 128
#define H 32
#define K 16
#define FOUT 10
#define EPSF 1e-15f
#define FULL 0xffffffffu
#define WSTR 36         // padded transposed-weight stride (144B = 9x16B aligned)
#define RS   260        // xs transpose stride (1040B aligned)
#define NTHR 512
#define NW   16         // warps per CTA
#define NPW  16         // nodes per warp
#define PH1  36         // padded h1 row stride (floats)
#define PH1Q 9          // h1 row stride in float4
#define PS   20         // padded s row stride (floats)
#define PSQ  5          // s row stride in float4

// ---------------- globals ----------------
__device__ float g_acc[2] = {0.f, 0.f};
__device__ int   g_ctr = 0;

// ---------------- f32x2 helpers ----------------
__device__ __forceinline__ unsigned long long pk2(float lo, float hi) {
    unsigned long long r;
    asm("mov.b64 %0, {%1,%2};" : "=l"(r)
        : "r"(__float_as_uint(lo)), "r"(__float_as_uint(hi)));
    return r;
}
__device__ __forceinline__ void fma2(unsigned long long& d,
                                     unsigned long long a, unsigned long long b) {
    asm("fma.rn.f32x2 %0, %1, %2, %0;" : "+l"(d) : "l"(a), "l"(b));
}
__device__ __forceinline__ void add2(unsigned long long& d, unsigned long long a) {
    asm("add.rn.f32x2 %0, %0, %1;" : "+l"(d) : "l"(a));
}
__device__ __forceinline__ void upk2(float& lo, float& hi, unsigned long long v) {
    unsigned int a, b2;
    asm("mov.b64 {%0,%1}, %2;" : "=r"(a), "=r"(b2) : "l"(v));
    lo = __uint_as_float(a); hi = __uint_as_float(b2);
}
__device__ __forceinline__ float hsum2(unsigned long long v) {
    float lo, hi; upk2(lo, hi, v); return lo + hi;
}

// ---------------- mega-kernel shared layout ----------------
struct SMem {
    float h1[N*PH1];          // padded rows
    float s[N*PS];            // padded; overlaid by ws[FIN*H] during lin1
    float wk[4096];           // aggb/hcb strips, reductions, conv2
    float wr[H*WSTR];
    float wo[H*WSTR];
    float wp[K*WSTR];
    float br[H];
    float bp[K];
    float px[K*H];
    float adj[K*K];
    float ssm[K*K];
    float red[32];
    float tbuf[NW*16];
    float sd[K];
    float sr[H];
    float sh3[H];
    float so[FOUT];
    int wscan[8];
    alignas(16) unsigned short idx[E_PER];  // overlaid by xs[16*RS] during lin1
    int deg[N];               // xs overlay spills 256B into deg (rewritten later)
    int start[N];
    int cnt[N];
};

// ---------------- mega: entire network, one CTA per graph, 512 threads ------
__global__ __launch_bounds__(NTHR, 2)
void k_mega(const float* __restrict__ x,
            const int* __restrict__ ei,
            const float* __restrict__ Wlin1, const float* __restrict__ blin1,
            const float* __restrict__ Wrel,  const float* __restrict__ brel,
            const float* __restrict__ Wroot, const float* __restrict__ Wpool,
            const float* __restrict__ bpool,
            const float* __restrict__ Wrel2, const float* __restrict__ brel2,
            const float* __restrict__ Wroot2,
            const float* __restrict__ Wlin2, const float* __restrict__ blin2,
            const float* __restrict__ Wlin3, const float* __restrict__ blin3,
            float* __restrict__ out, int out_size)
{
    extern __shared__ char smraw[];
    SMem* sm = (SMem*)smraw;
    int b = blockIdx.x, tid = threadIdx.x;
    int w = tid >> 5, lane = tid & 31;
    int base = b * N;

    // ---- stage conv/pool weights early ----
    for (int i = tid; i < H*H; i += NTHR) {
        int k = i >> 5, l = i & 31;
        sm->wr[l*WSTR + k] = Wrel[i];
        sm->wo[l*WSTR + k] = Wroot[i];
    }
    for (int i = tid; i < H*K; i += NTHR) {
        int k = i >> 4, l = i & 15;
        sm->wp[l*WSTR + k] = Wpool[i];
    }
    if (tid < H) sm->br[tid] = brel[tid];
    if (tid < K) sm->bp[tid] = bpool[tid];
    if (tid < N) sm->cnt[tid] = 0;

    // ================= fused lin1: h1 = x[b] @ W1 + b1 (FFMA2 tile) ==========
    {
        float* ws = sm->s;                 // overlay
        float* xs = (float*)sm->idx;       // overlay
        for (int i = tid; i < FIN*H; i += NTHR) ws[i] = Wlin1[i];

        int c0 = (tid & 7) * 4;
        int r0 = (tid >> 3) * 4;
        int lr = tid >> 2;
        int q  = tid & 3;

        float bsv[4];
#pragma unroll
        for (int c = 0; c < 4; c++) bsv[c] = blin1[c0 + c];

        const float* xg = x + (size_t)base * FIN;
        float4 nx[2];
#pragma unroll
        for (int p = 0; p < 2; p++)
            nx[p] = *(const float4*)&xg[(size_t)(lr + p*128)*FIN + q*4];

        unsigned long long acc[2][4];
#pragma unroll
        for (int pr = 0; pr < 2; pr++)
#pragma unroll
            for (int c = 0; c < 4; c++)
                acc[pr][c] = pk2(bsv[c], bsv[c]);

        for (int kt = 0; kt < 8; kt++) {
            __syncthreads();
#pragma unroll
            for (int p = 0; p < 2; p++) {
                int row = lr + p*128;
                xs[(q*4+0)*RS + row] = nx[p].x;
                xs[(q*4+1)*RS + row] = nx[p].y;
                xs[(q*4+2)*RS + row] = nx[p].z;
                xs[(q*4+3)*RS + row] = nx[p].w;
            }
            __syncthreads();
            if (kt < 7) {
#pragma unroll
                for (int p = 0; p < 2; p++)
                    nx[p] = *(const float4*)&xg[(size_t)(lr + p*128)*FIN + (kt+1)*16 + q*4];
            }
#pragma unroll
            for (int k = 0; k < 16; k++) {
                float4 wv = *(const float4*)&ws[(kt*16 + k)*H + c0];
                float4 xa = *(const float4*)&xs[k*RS + r0];
                unsigned long long xp[2], wp2[4];
                xp[0] = pk2(xa.x, xa.y); xp[1] = pk2(xa.z, xa.w);
                wp2[0] = pk2(wv.x, wv.x); wp2[1] = pk2(wv.y, wv.y);
                wp2[2] = pk2(wv.z, wv.z); wp2[3] = pk2(wv.w, wv.w);
#pragma unroll
                for (int pr = 0; pr < 2; pr++) {
                    fma2(acc[pr][0], xp[pr], wp2[0]);
                    fma2(acc[pr][1], xp[pr], wp2[1]);
                    fma2(acc[pr][2], xp[pr], wp2[2]);
                    fma2(acc[pr][3], xp[pr], wp2[3]);
                }
            }
        }
#pragma unroll
        for (int pr = 0; pr < 2; pr++) {
            float lo[4], hi[4];
#pragma unroll
            for (int c = 0; c < 4; c++) upk2(lo[c], hi[c], acc[pr][c]);
            int gr = r0 + 2*pr;
            *(float4*)&sm->h1[gr*PH1 + c0]     = make_float4(lo[0], lo[1], lo[2], lo[3]);
            *(float4*)&sm->h1[(gr+1)*PH1 + c0] = make_float4(hi[0], hi[1], hi[2], hi[3]);
        }
    }
    __syncthreads();

    // ---- sort edges by src (count, warp-level scan, scatter) ----
    const int* srcg = ei + b*E_PER;
    const int* dstg = ei + ET + b*E_PER;
#pragma unroll
    for (int i = 0; i < E_PER/NTHR; i++)
        atomicAdd(&sm->cnt[srcg[tid + i*NTHR] - base], 1);
    __syncthreads();
    {
        int d0 = 0, st0 = 0;
        if (tid < N) {
            d0 = sm->cnt[tid];
            int v = d0;
#pragma unroll
            for (int off = 1; off < 32; off <<= 1) {
                int nv = __shfl_up_sync(FULL, v, off);
                if (lane >= off) v += nv;
            }
            if (lane == 31) sm->wscan[w] = v;
            st0 = v - d0;
        }
        __syncthreads();
        if (tid < 8) {
            int t = sm->wscan[tid];
#pragma unroll
            for (int off = 1; off < 8; off <<= 1) {
                int nv = __shfl_up_sync(0xff, t, off);
                if (tid >= off) t += nv;
            }
            sm->wscan[tid] = t;   // inclusive warp totals
        }
        __syncthreads();
        if (tid < N) {
            if (w > 0) st0 += sm->wscan[w-1];
            sm->deg[tid] = d0;
            sm->start[tid] = st0;
            sm->cnt[tid] = st0;
        }
    }
    __syncthreads();
#pragma unroll
    for (int i = 0; i < E_PER/NTHR; i++) {
        int u = srcg[tid + i*NTHR] - base;
        int p = atomicAdd(&sm->cnt[u], 1);
        sm->idx[p] = (unsigned short)(dstg[tid + i*NTHR] - base);
    }
    __syncthreads();

    // ---- Phase A: 4-node batches — gather (ADD2), FMA2 transform, pool ----
    float px_reg[16];
#pragma unroll
    for (int k = 0; k < 16; k++) px_reg[k] = 0.f;

    {
        int grp = lane >> 3, q8 = lane & 7;
        const float4* h1r = (const float4*)sm->h1;
        float* aggb = sm->wk + w*128;          // 4 nodes x 32
        float* hcb  = sm->wk + 2048 + w*128;   // 4 nodes x 32

        for (int u0 = w*NPW; u0 < w*NPW + NPW; u0 += 4) {
            // gather 4 nodes (packed f32x2 accumulation, MLP=2)
#pragma unroll
            for (int g = 0; g < 4; g++) {
                int u = u0 + g;
                int d  = sm->deg[u];
                int st = sm->start[u];
                ulonglong2 A0 = make_ulonglong2(0ull, 0ull);
                ulonglong2 A1 = make_ulonglong2(0ull, 0ull);
                int i = grp;
                for (; i + 4 < d; i += 8) {
                    int v0 = sm->idx[st + i];
                    int v1 = sm->idx[st + i + 4];
                    ulonglong2 r0 = *(const ulonglong2*)&h1r[v0*PH1Q + q8];
                    ulonglong2 r1 = *(const ulonglong2*)&h1r[v1*PH1Q + q8];
                    add2(A0.x, r0.x); add2(A0.y, r0.y);
                    add2(A1.x, r1.x); add2(A1.y, r1.y);
                }
                if (i < d) {
                    int v0 = sm->idx[st + i];
                    ulonglong2 r0 = *(const ulonglong2*)&h1r[v0*PH1Q + q8];
                    add2(A0.x, r0.x); add2(A0.y, r0.y);
                }
                add2(A0.x, A1.x); add2(A0.y, A1.y);
                unsigned long long t;
                t = __shfl_xor_sync(FULL, A0.x, 8);  add2(A0.x, t);
                t = __shfl_xor_sync(FULL, A0.x, 16); add2(A0.x, t);
                t = __shfl_xor_sync(FULL, A0.y, 8);  add2(A0.y, t);
                t = __shfl_xor_sync(FULL, A0.y, 16); add2(A0.y, t);
                if (lane < 8) *(ulonglong2*)&aggb[g*32 + lane*4] = A0;
            }
            __syncwarp();

            // transform: packed FMA2, weights amortized over 4 nodes
            unsigned long long acc2[4];
#pragma unroll
            for (int g = 0; g < 4; g++) acc2[g] = 0ull;
#pragma unroll
            for (int c = 0; c < 8; c++) {
                ulonglong2 wr2 = *(const ulonglong2*)&sm->wr[lane*WSTR + 4*c];
                ulonglong2 wo2 = *(const ulonglong2*)&sm->wo[lane*WSTR + 4*c];
#pragma unroll
                for (int g = 0; g < 4; g++) {
                    ulonglong2 av2 = *(const ulonglong2*)&aggb[g*32 + 4*c];
                    ulonglong2 hv2 = *(const ulonglong2*)&sm->h1[(u0+g)*PH1 + 4*c];
                    fma2(acc2[g], av2.x, wr2.x);
                    fma2(acc2[g], av2.y, wr2.y);
                    fma2(acc2[g], hv2.x, wo2.x);
                    fma2(acc2[g], hv2.y, wo2.y);
                }
            }
            float o[4];
#pragma unroll
            for (int g = 0; g < 4; g++) {
                o[g] = sm->br[lane] + hsum2(acc2[g]);
                hcb[g*32 + lane] = o[g];
            }
            __syncwarp();

            // pool logits: packed FMA2, wp amortized
            int lk = lane & 15;
            unsigned long long sacc[4];
#pragma unroll
            for (int g = 0; g < 4; g++) sacc[g] = 0ull;
#pragma unroll
            for (int c = 0; c < 8; c++) {
                ulonglong2 wp2 = *(const ulonglong2*)&sm->wp[lk*WSTR + 4*c];
#pragma unroll
                for (int g = 0; g < 4; g++) {
                    ulonglong2 hq2 = *(const ulonglong2*)&hcb[g*32 + 4*c];
                    fma2(sacc[g], hq2.x, wp2.x);
                    fma2(sacc[g], hq2.y, wp2.y);
                }
            }
            // softmax + s store + px rank-1, per node
#pragma unroll
            for (int g = 0; g < 4; g++) {
                float sl = sm->bp[lk] + hsum2(sacc[g]);
                float m = sl;
#pragma unroll
                for (int off = 8; off >= 1; off >>= 1)
                    m = fmaxf(m, __shfl_xor_sync(FULL, m, off, 16));
                float e = __expf(sl - m);
                float sum = e;
#pragma unroll
                for (int off = 8; off >= 1; off >>= 1)
                    sum += __shfl_xor_sync(FULL, sum, off, 16);
                float svx = e / sum;
                if (lane < 16) sm->s[(u0+g)*PS + lk] = svx;
#pragma unroll
                for (int k = 0; k < 16; k++) {
                    float sk = __shfl_sync(FULL, svx, k);
                    px_reg[k] += sk * o[g];
                }
            }
        }
    }
    __syncthreads();

    // ---- px reduction across 16 warps (2 rounds of 8 via wk) ----
    for (int round = 0; round < 2; round++) {
        if ((w >> 3) == round) {
#pragma unroll
            for (int k = 0; k < 16; k++)
                sm->wk[(w & 7)*512 + k*32 + lane] = px_reg[k];
        }
        __syncthreads();
        {
            float v = 0.f;
#pragma unroll
            for (int ww = 0; ww < 8; ww++) v += sm->wk[ww*512 + tid];
            if (round == 0) sm->px[tid] = v; else sm->px[tid] += v;
        }
        __syncthreads();
    }

    // ---- Phase B: t = A@s (ADD2, MLP=2); out_adj = s^T t, ss, den ----
    float oa[8], ob[8];
#pragma unroll
    for (int i = 0; i < 8; i++) { oa[i] = 0.f; ob[i] = 0.f; }
    float den_acc = 0.f;
    {
        int grp8 = lane >> 2, q4 = lane & 3;
        int j = lane & 15, kh = lane >> 4;
        const float4* ssr = (const float4*)sm->s;
        for (int u = w*NPW; u < w*NPW + NPW; u++) {
            int d  = sm->deg[u];
            int st = sm->start[u];
            ulonglong2 A0 = make_ulonglong2(0ull, 0ull);
            ulonglong2 A1 = make_ulonglong2(0ull, 0ull);
            int i = grp8;
            for (; i + 8 < d; i += 16) {
                int v0 = sm->idx[st + i];
                int v1 = sm->idx[st + i + 8];
                ulonglong2 r0 = *(const ulonglong2*)&ssr[v0*PSQ + q4];
                ulonglong2 r1 = *(const ulonglong2*)&ssr[v1*PSQ + q4];
                add2(A0.x, r0.x); add2(A0.y, r0.y);
                add2(A1.x, r1.x); add2(A1.y, r1.y);
            }
            if (i < d) {
                int v0 = sm->idx[st + i];
                ulonglong2 r0 = *(const ulonglong2*)&ssr[v0*PSQ + q4];
                add2(A0.x, r0.x); add2(A0.y, r0.y);
            }
            add2(A0.x, A1.x); add2(A0.y, A1.y);
            unsigned long long t;
            t = __shfl_xor_sync(FULL, A0.x, 4);  add2(A0.x, t);
            t = __shfl_xor_sync(FULL, A0.x, 8);  add2(A0.x, t);
            t = __shfl_xor_sync(FULL, A0.x, 16); add2(A0.x, t);
            t = __shfl_xor_sync(FULL, A0.y, 4);  add2(A0.y, t);
            t = __shfl_xor_sync(FULL, A0.y, 8);  add2(A0.y, t);
            t = __shfl_xor_sync(FULL, A0.y, 16); add2(A0.y, t);
            if (lane < 4) *(ulonglong2*)&sm->tbuf[w*16 + lane*4] = A0;
            __syncwarp();
            float tj = sm->tbuf[w*16 + j];
            float sj = sm->s[u*PS + j];
            __syncwarp();

            float v2 = sj*sj;
            v2 += __shfl_xor_sync(FULL, v2, 1, 16);
            v2 += __shfl_xor_sync(FULL, v2, 2, 16);
            v2 += __shfl_xor_sync(FULL, v2, 4, 16);
            v2 += __shfl_xor_sync(FULL, v2, 8, 16);
            den_acc += (float)d * v2;

#pragma unroll
            for (int kk = 0; kk < 8; kk++) {
                float su = sm->s[u*PS + kh*8 + kk];
                oa[kk] += su * tj;
                ob[kk] += su * sj;
            }
        }
    }
    __syncthreads();

    // ---- reduce out_adj + ss + den (2 rounds of 8 warps, both at once) ----
    {
        int j = lane & 15, kh = lane >> 4;
        if (lane == 0) sm->red[w] = den_acc;
        for (int round = 0; round < 2; round++) {
            if ((w >> 3) == round) {
#pragma unroll
                for (int kk = 0; kk < 8; kk++) {
                    sm->wk[(w & 7)*256 + (kh*8+kk)*16 + j] = oa[kk];
                    sm->wk[2048 + (w & 7)*256 + (kh*8+kk)*16 + j] = ob[kk];
                }
            }
            __syncthreads();
            if (tid < 256) {
                float v = 0.f, v2 = 0.f;
#pragma unroll
                for (int ww = 0; ww < 8; ww++) {
                    v  += sm->wk[ww*256 + tid];
                    v2 += sm->wk[2048 + ww*256 + tid];
                }
                if (round == 0) { sm->adj[tid] = v; sm->ssm[tid] = v2; }
                else            { sm->adj[tid] += v; sm->ssm[tid] += v2; }
            }
            __syncthreads();
        }
    }

    // ---- losses (CTA partials -> global atomics) ----
    int kq = (tid >> 4) & 15, jq = tid & 15;
    float mincut_part = 0.f;
    if (tid == 0) {
        float den = 0.f;
        for (int i = 0; i < NW; i++) den += sm->red[i];
        float num = 0.f;
        for (int kk = 0; kk < K; kk++) num += sm->adj[kk*K + kk];
        mincut_part = -(num / den);
    }
    float ssv = (tid < 256) ? sm->ssm[tid] : 0.f;
    if (tid < 256) sm->wk[tid] = ssv * ssv;
    __syncthreads();
    for (int off = 128; off > 0; off >>= 1) { if (tid < off) sm->wk[tid] += sm->wk[tid + off]; __syncthreads(); }
    float nrm = sqrtf(sm->wk[0]);
    __syncthreads();
    if (tid < 256) {
        float diff = ssv / nrm - ((kq == jq) ? 0.25f : 0.f);
        sm->wk[tid] = diff * diff;
    }
    __syncthreads();
    for (int off = 128; off > 0; off >>= 1) { if (tid < off) sm->wk[tid] += sm->wk[tid + off]; __syncthreads(); }
    float ortho_part = (tid == 0) ? sqrtf(sm->wk[0]) : 0.f;
    __syncthreads();

    // ---- normalize out_adj ----
    if (tid < 256) {
        float av = (kq == jq) ? 0.f : sm->adj[tid];
        sm->adj[tid] = av;
    }
    __syncthreads();
    if (tid < K) {
        float rs = 0.f;
        for (int jj = 0; jj < K; jj++) rs += sm->adj[tid*K + jj];
        sm->sd[tid] = sqrtf(rs) + EPSF;
    }
    __syncthreads();
    if (tid < 256) sm->adj[tid] = sm->adj[tid] / (sm->sd[kq] * sm->sd[jq]);
    __syncthreads();

    // ---- conv2 on pooled features (one (kc,h) per thread) ----
    {
        int h = tid & 31, kc = tid >> 5;
        float m1 = 0.f;
#pragma unroll
        for (int jj = 0; jj < K; jj++) m1 += sm->adj[kc*K + jj] * sm->px[jj*H + h];
        sm->wk[kc*H + h] = m1;
    }
    __syncthreads();
    {
        int h = tid & 31, kc = tid >> 5;
        float acc = brel2[h];
        for (int c = 0; c < H; c++)
            acc += sm->wk[kc*H + c] * Wrel2[c*H + h] + sm->px[kc*H + c] * Wroot2[c*H + h];
        sm->wk[512 + kc*H + h] = acc;
    }
    __syncthreads();

    // ---- readout + MLP + log_softmax ----
    if (tid < H) {
        float r = 0.f;
#pragma unroll
        for (int kk = 0; kk < K; kk++) r += sm->wk[512 + kk*H + tid];
        sm->sr[tid] = r;
    }
    __syncthreads();
    if (tid < H) {
        float a2 = blin2[tid];
        for (int c = 0; c < H; c++) a2 += sm->sr[c] * Wlin2[c*H + tid];
        sm->sh3[tid] = fmaxf(a2, 0.f);
    }
    __syncthreads();
    if (tid < FOUT) {
        float a3 = blin3[tid];
        for (int c = 0; c < H; c++) a3 += sm->sh3[c] * Wlin3[c*FOUT + tid];
        sm->so[tid] = a3;
    }
    __syncthreads();
    if (tid == 0) {
        float m = sm->so[0];
        for (int i = 1; i < FOUT; i++) m = fmaxf(m, sm->so[i]);
        float s = 0.f;
        for (int i = 0; i < FOUT; i++) s += __expf(sm->so[i] - m);
        float lse = m + __logf(s);
        for (int i = 0; i < FOUT; i++) out[b*FOUT + i] = sm->so[i] - lse;

        // global loss reduction; last CTA writes + resets (graph-replay safe)
        atomicAdd(&g_acc[0], mincut_part * (1.f/(float)B));
        atomicAdd(&g_acc[1], ortho_part  * (1.f/(float)B));
        __threadfence();
        int old = atomicAdd(&g_ctr, 1);
        if (old == B - 1) {
            __threadfence();
            float l0 = g_acc[0], l1 = g_acc[1];
            if (out_size > B*FOUT)     out[B*FOUT]     = l0;
            if (out_size > B*FOUT + 1) out[B*FOUT + 1] = l1;
            g_acc[0] = 0.f; g_acc[1] = 0.f;
            g_ctr = 0;
            __threadfence();
        }
    }
}

// ---------------- launch ----------------
extern "C" void kernel_launch(void* const* d_in, const int* in_sizes, int n_in,
                              void* d_out, int out_size) {
    const float* x     = (const float*)d_in[0];
    const int*   ei    = (const int*)d_in[1];
    const float* Wlin1 = (const float*)d_in[3];
    const float* blin1 = (const float*)d_in[4];
    const float* Wrel1 = (const float*)d_in[5];
    const float* brel1 = (const float*)d_in[6];
    const float* Wroot1= (const float*)d_in[7];
    const float* Wpool = (const float*)d_in[8];
    const float* bpool = (const float*)d_in[9];
    const float* Wrel2 = (const float*)d_in[10];
    const float* brel2 = (const float*)d_in[11];
    const float* Wroot2= (const float*)d_in[12];
    const float* Wlin2 = (const float*)d_in[13];
    const float* blin2 = (const float*)d_in[14];
    const float* Wlin3 = (const float*)d_in[15];
    const float* blin3 = (const float*)d_in[16];
    float* out = (float*)d_out;

    cudaFuncSetAttribute(k_mega, cudaFuncAttributeMaxDynamicSharedMemorySize,
                         (int)sizeof(SMem));

    k_mega<<<B, NTHR, sizeof(SMem)>>>(x, ei, Wlin1, blin1,
                                      Wrel1, brel1, Wroot1, Wpool, bpool,
                                      Wrel2, brel2, Wroot2,
                                      Wlin2, blin2, Wlin3, blin3, out, out_size);
}

// round 14
// speedup vs baseline: 1.3028x; 1.0668x over previous
#include <cuda_runtime.h>

#define B 512
#define N 256
#define E_PER 8192
#define NT (B*N)
#define ET (B*E_PER)
#define FIN 128
#define H 32
#define K 16
#define FOUT 10
#define EPSF 1e-15f
#define FULL 0xffffffffu
#define WSTR 36         // padded transposed-weight stride (144B, 16B-aligned)
#define RS   260        // xs transpose stride
#define NTHR 512
#define NW   16         // warps per CTA
#define NPW  16         // nodes per warp
#define PH1  32         // h1 row stride (floats)  — padding proved useless (R12)
#define PH1Q 8          // h1 row stride in float4
#define PS   16         // s row stride (floats)
#define PSQ  4          // s row stride in float4

// ---------------- globals ----------------
__device__ float g_acc[2] = {0.f, 0.f};
__device__ int   g_ctr = 0;

// ---------------- f32x2 helpers ----------------
__device__ __forceinline__ unsigned long long pk2(float lo, float hi) {
    unsigned long long r;
    asm("mov.b64 %0, {%1,%2};" : "=l"(r)
        : "r"(__float_as_uint(lo)), "r"(__float_as_uint(hi)));
    return r;
}
__device__ __forceinline__ void fma2(unsigned long long& d,
                                     unsigned long long a, unsigned long long b) {
    asm("fma.rn.f32x2 %0, %1, %2, %0;" : "+l"(d) : "l"(a), "l"(b));
}
__device__ __forceinline__ void add2(unsigned long long& d, unsigned long long a) {
    asm("add.rn.f32x2 %0, %0, %1;" : "+l"(d) : "l"(a));
}
__device__ __forceinline__ void upk2(float& lo, float& hi, unsigned long long v) {
    unsigned int a, b2;
    asm("mov.b64 {%0,%1}, %2;" : "=r"(a), "=r"(b2) : "l"(v));
    lo = __uint_as_float(a); hi = __uint_as_float(b2);
}
__device__ __forceinline__ float hsum2(unsigned long long v) {
    float lo, hi; upk2(lo, hi, v); return lo + hi;
}

// ---------------- mega-kernel shared layout ----------------
struct SMem {
    float h1[N*PH1];          // 32768 B
    float s[N*PS];            // 16384 B; overlaid by ws[FIN*H] during lin1
    float wk[4096];           // 16384 B: aggb/hcb strips, reductions, conv2
    float wr[H*WSTR];
    float wo[H*WSTR];
    float wp[K*WSTR];
    float br[H];
    float bp[K];
    float px[K*H];
    float adj[K*K];
    float ssm[K*K];
    float red[32];
    float tbuf[NW*16];
    float sd[K];
    float sr[H];
    float sh3[H];
    float so[FOUT];
    int wscan[8];
    alignas(16) unsigned short idx[E_PER];  // overlaid by xs[16*RS] during lin1
    int deg[N];               // xs overlay spills 256B into deg (rewritten later)
    int start[N];
    int cnt[N];
};

// ---------------- mega: entire network, one CTA per graph, 512 threads ------
__global__ __launch_bounds__(NTHR, 2)
void k_mega(const float* __restrict__ x,
            const int* __restrict__ ei,
            const float* __restrict__ Wlin1, const float* __restrict__ blin1,
            const float* __restrict__ Wrel,  const float* __restrict__ brel,
            const float* __restrict__ Wroot, const float* __restrict__ Wpool,
            const float* __restrict__ bpool,
            const float* __restrict__ Wrel2, const float* __restrict__ brel2,
            const float* __restrict__ Wroot2,
            const float* __restrict__ Wlin2, const float* __restrict__ blin2,
            const float* __restrict__ Wlin3, const float* __restrict__ blin3,
            float* __restrict__ out, int out_size)
{
    extern __shared__ char smraw[];
    SMem* sm = (SMem*)smraw;
    int b = blockIdx.x, tid = threadIdx.x;
    int w = tid >> 5, lane = tid & 31;
    int base = b * N;

    // ---- stage conv/pool weights early ----
    for (int i = tid; i < H*H; i += NTHR) {
        int k = i >> 5, l = i & 31;
        sm->wr[l*WSTR + k] = Wrel[i];
        sm->wo[l*WSTR + k] = Wroot[i];
    }
    for (int i = tid; i < H*K; i += NTHR) {
        int k = i >> 4, l = i & 15;
        sm->wp[l*WSTR + k] = Wpool[i];
    }
    if (tid < H) sm->br[tid] = brel[tid];
    if (tid < K) sm->bp[tid] = bpool[tid];
    if (tid < N) sm->cnt[tid] = 0;

    // ================= fused lin1: h1 = x[b] @ W1 + b1 (FFMA2 tile) ==========
    {
        float* ws = sm->s;                 // overlay (16384 B exactly)
        float* xs = (float*)sm->idx;       // overlay
        for (int i = tid; i < FIN*H; i += NTHR) ws[i] = Wlin1[i];

        int c0 = (tid & 7) * 4;
        int r0 = (tid >> 3) * 4;
        int lr = tid >> 2;
        int q  = tid & 3;

        float bsv[4];
#pragma unroll
        for (int c = 0; c < 4; c++) bsv[c] = blin1[c0 + c];

        const float* xg = x + (size_t)base * FIN;
        float4 nx[2];
#pragma unroll
        for (int p = 0; p < 2; p++)
            nx[p] = *(const float4*)&xg[(size_t)(lr + p*128)*FIN + q*4];

        unsigned long long acc[2][4];
#pragma unroll
        for (int pr = 0; pr < 2; pr++)
#pragma unroll
            for (int c = 0; c < 4; c++)
                acc[pr][c] = pk2(bsv[c], bsv[c]);

        for (int kt = 0; kt < 8; kt++) {
            __syncthreads();
#pragma unroll
            for (int p = 0; p < 2; p++) {
                int row = lr + p*128;
                xs[(q*4+0)*RS + row] = nx[p].x;
                xs[(q*4+1)*RS + row] = nx[p].y;
                xs[(q*4+2)*RS + row] = nx[p].z;
                xs[(q*4+3)*RS + row] = nx[p].w;
            }
            __syncthreads();
            if (kt < 7) {
#pragma unroll
                for (int p = 0; p < 2; p++)
                    nx[p] = *(const float4*)&xg[(size_t)(lr + p*128)*FIN + (kt+1)*16 + q*4];
            }
#pragma unroll
            for (int k = 0; k < 16; k++) {
                float4 wv = *(const float4*)&ws[(kt*16 + k)*H + c0];
                float4 xa = *(const float4*)&xs[k*RS + r0];
                unsigned long long xp[2], wp2[4];
                xp[0] = pk2(xa.x, xa.y); xp[1] = pk2(xa.z, xa.w);
                wp2[0] = pk2(wv.x, wv.x); wp2[1] = pk2(wv.y, wv.y);
                wp2[2] = pk2(wv.z, wv.z); wp2[3] = pk2(wv.w, wv.w);
#pragma unroll
                for (int pr = 0; pr < 2; pr++) {
                    fma2(acc[pr][0], xp[pr], wp2[0]);
                    fma2(acc[pr][1], xp[pr], wp2[1]);
                    fma2(acc[pr][2], xp[pr], wp2[2]);
                    fma2(acc[pr][3], xp[pr], wp2[3]);
                }
            }
        }
#pragma unroll
        for (int pr = 0; pr < 2; pr++) {
            float lo[4], hi[4];
#pragma unroll
            for (int c = 0; c < 4; c++) upk2(lo[c], hi[c], acc[pr][c]);
            int gr = r0 + 2*pr;
            *(float4*)&sm->h1[gr*PH1 + c0]     = make_float4(lo[0], lo[1], lo[2], lo[3]);
            *(float4*)&sm->h1[(gr+1)*PH1 + c0] = make_float4(hi[0], hi[1], hi[2], hi[3]);
        }
    }
    __syncthreads();

    // ---- sort edges by src (count, warp-level scan, scatter) ----
    const int* srcg = ei + b*E_PER;
    const int* dstg = ei + ET + b*E_PER;
#pragma unroll
    for (int i = 0; i < E_PER/NTHR; i++)
        atomicAdd(&sm->cnt[srcg[tid + i*NTHR] - base], 1);
    __syncthreads();
    {
        int d0 = 0, st0 = 0;
        if (tid < N) {
            d0 = sm->cnt[tid];
            int v = d0;
#pragma unroll
            for (int off = 1; off < 32; off <<= 1) {
                int nv = __shfl_up_sync(FULL, v, off);
                if (lane >= off) v += nv;
            }
            if (lane == 31) sm->wscan[w] = v;
            st0 = v - d0;
        }
        __syncthreads();
        if (tid < 8) {
            int t = sm->wscan[tid];
#pragma unroll
            for (int off = 1; off < 8; off <<= 1) {
                int nv = __shfl_up_sync(0xff, t, off);
                if (tid >= off) t += nv;
            }
            sm->wscan[tid] = t;
        }
        __syncthreads();
        if (tid < N) {
            if (w > 0) st0 += sm->wscan[w-1];
            sm->deg[tid] = d0;
            sm->start[tid] = st0;
            sm->cnt[tid] = st0;
        }
    }
    __syncthreads();
#pragma unroll
    for (int i = 0; i < E_PER/NTHR; i++) {
        int u = srcg[tid + i*NTHR] - base;
        int p = atomicAdd(&sm->cnt[u], 1);
        sm->idx[p] = (unsigned short)(dstg[tid + i*NTHR] - base);
    }
    __syncthreads();

    // ---- Phase A: 4-node batches; paired pool/softmax; f32x2 px ----
    unsigned long long px2[8];
#pragma unroll
    for (int k = 0; k < 8; k++) px2[k] = 0ull;

    {
        int grp = lane >> 3, q8 = lane & 7;
        int lk = lane & 15, half = lane >> 4;
        float brv = sm->br[lane];
        float bpv = sm->bp[lk];
        const float4* h1r = (const float4*)sm->h1;
        float* aggb = sm->wk + w*128;          // 4 nodes x 32
        float* hcb  = sm->wk + 2048 + w*128;   // 4 nodes x 32

        for (int u0 = w*NPW; u0 < w*NPW + NPW; u0 += 4) {
            // gather 4 nodes (packed f32x2 accumulation, MLP=2)
#pragma unroll
            for (int g = 0; g < 4; g++) {
                int u = u0 + g;
                int d  = sm->deg[u];
                int st = sm->start[u];
                ulonglong2 A0 = make_ulonglong2(0ull, 0ull);
                ulonglong2 A1 = make_ulonglong2(0ull, 0ull);
                int i = grp;
                for (; i + 4 < d; i += 8) {
                    int v0 = sm->idx[st + i];
                    int v1 = sm->idx[st + i + 4];
                    ulonglong2 r0 = *(const ulonglong2*)&h1r[v0*PH1Q + q8];
                    ulonglong2 r1 = *(const ulonglong2*)&h1r[v1*PH1Q + q8];
                    add2(A0.x, r0.x); add2(A0.y, r0.y);
                    add2(A1.x, r1.x); add2(A1.y, r1.y);
                }
                if (i < d) {
                    int v0 = sm->idx[st + i];
                    ulonglong2 r0 = *(const ulonglong2*)&h1r[v0*PH1Q + q8];
                    add2(A0.x, r0.x); add2(A0.y, r0.y);
                }
                add2(A0.x, A1.x); add2(A0.y, A1.y);
                unsigned long long t;
                t = __shfl_xor_sync(FULL, A0.x, 8);  add2(A0.x, t);
                t = __shfl_xor_sync(FULL, A0.x, 16); add2(A0.x, t);
                t = __shfl_xor_sync(FULL, A0.y, 8);  add2(A0.y, t);
                t = __shfl_xor_sync(FULL, A0.y, 16); add2(A0.y, t);
                if (lane < 8) *(ulonglong2*)&aggb[g*32 + lane*4] = A0;
            }
            __syncwarp();

            // transform: packed FMA2, weights amortized over 4 nodes
            unsigned long long acc2[4];
#pragma unroll
            for (int g = 0; g < 4; g++) acc2[g] = 0ull;
#pragma unroll
            for (int c = 0; c < 8; c++) {
                ulonglong2 wr2 = *(const ulonglong2*)&sm->wr[lane*WSTR + 4*c];
                ulonglong2 wo2 = *(const ulonglong2*)&sm->wo[lane*WSTR + 4*c];
#pragma unroll
                for (int g = 0; g < 4; g++) {
                    ulonglong2 av2 = *(const ulonglong2*)&aggb[g*32 + 4*c];
                    ulonglong2 hv2 = *(const ulonglong2*)&sm->h1[(u0+g)*PH1 + 4*c];
                    fma2(acc2[g], av2.x, wr2.x);
                    fma2(acc2[g], av2.y, wr2.y);
                    fma2(acc2[g], hv2.x, wo2.x);
                    fma2(acc2[g], hv2.y, wo2.y);
                }
            }
            float o[4];
#pragma unroll
            for (int g = 0; g < 4; g++) {
                o[g] = brv + hsum2(acc2[g]);
                hcb[g*32 + lane] = o[g];
            }
            __syncwarp();

            // pool+softmax PAIRED: each 16-lane half handles a different node
#pragma unroll
            for (int p = 0; p < 2; p++) {
                int g = 2*p + half;      // node this half processes
                unsigned long long sacc = 0ull;
#pragma unroll
                for (int c = 0; c < 8; c++) {
                    ulonglong2 wp2 = *(const ulonglong2*)&sm->wp[lk*WSTR + 4*c];
                    ulonglong2 hq2 = *(const ulonglong2*)&hcb[g*32 + 4*c];
                    fma2(sacc, hq2.x, wp2.x);
                    fma2(sacc, hq2.y, wp2.y);
                }
                float sl = bpv + hsum2(sacc);
                // softmax without max-subtraction (logits bounded for this net)
                float e = __expf(sl);
                float sum = e;
#pragma unroll
                for (int off = 8; off >= 1; off >>= 1)
                    sum += __shfl_xor_sync(FULL, sum, off, 16);
                float svx = e / sum;
                sm->s[(u0+g)*PS + lk] = svx;
            }
            __syncwarp();

            // px rank-1 updates via broadcast LDS.64 + FMA2
#pragma unroll
            for (int g = 0; g < 4; g++) {
                unsigned long long o2 = pk2(o[g], o[g]);
                const unsigned long long* srow =
                    (const unsigned long long*)&sm->s[(u0+g)*PS];
#pragma unroll
                for (int kk = 0; kk < 8; kk++)
                    fma2(px2[kk], srow[kk], o2);
            }
        }
    }
    __syncthreads();

    // ---- px reduction across 16 warps (2 rounds of 8 via wk) ----
    float px_reg[16];
#pragma unroll
    for (int kk = 0; kk < 8; kk++) upk2(px_reg[2*kk], px_reg[2*kk+1], px2[kk]);
    for (int round = 0; round < 2; round++) {
        if ((w >> 3) == round) {
#pragma unroll
            for (int k = 0; k < 16; k++)
                sm->wk[(w & 7)*512 + k*32 + lane] = px_reg[k];
        }
        __syncthreads();
        {
            float v = 0.f;
#pragma unroll
            for (int ww = 0; ww < 8; ww++) v += sm->wk[ww*512 + tid];
            if (round == 0) sm->px[tid] = v; else sm->px[tid] += v;
        }
        __syncthreads();
    }

    // ---- Phase B: t = A@s (ADD2, MLP=2); out_adj = s^T t, ss, den ----
    float oa[8], ob[8];
#pragma unroll
    for (int i = 0; i < 8; i++) { oa[i] = 0.f; ob[i] = 0.f; }
    float den_acc = 0.f;
    {
        int grp8 = lane >> 2, q4 = lane & 3;
        int j = lane & 15, kh = lane >> 4;
        const float4* ssr = (const float4*)sm->s;
        for (int u = w*NPW; u < w*NPW + NPW; u++) {
            int d  = sm->deg[u];
            int st = sm->start[u];
            ulonglong2 A0 = make_ulonglong2(0ull, 0ull);
            ulonglong2 A1 = make_ulonglong2(0ull, 0ull);
            int i = grp8;
            for (; i + 8 < d; i += 16) {
                int v0 = sm->idx[st + i];
                int v1 = sm->idx[st + i + 8];
                ulonglong2 r0 = *(const ulonglong2*)&ssr[v0*PSQ + q4];
                ulonglong2 r1 = *(const ulonglong2*)&ssr[v1*PSQ + q4];
                add2(A0.x, r0.x); add2(A0.y, r0.y);
                add2(A1.x, r1.x); add2(A1.y, r1.y);
            }
            if (i < d) {
                int v0 = sm->idx[st + i];
                ulonglong2 r0 = *(const ulonglong2*)&ssr[v0*PSQ + q4];
                add2(A0.x, r0.x); add2(A0.y, r0.y);
            }
            add2(A0.x, A1.x); add2(A0.y, A1.y);
            unsigned long long t;
            t = __shfl_xor_sync(FULL, A0.x, 4);  add2(A0.x, t);
            t = __shfl_xor_sync(FULL, A0.x, 8);  add2(A0.x, t);
            t = __shfl_xor_sync(FULL, A0.x, 16); add2(A0.x, t);
            t = __shfl_xor_sync(FULL, A0.y, 4);  add2(A0.y, t);
            t = __shfl_xor_sync(FULL, A0.y, 8);  add2(A0.y, t);
            t = __shfl_xor_sync(FULL, A0.y, 16); add2(A0.y, t);
            if (lane < 4) *(ulonglong2*)&sm->tbuf[w*16 + lane*4] = A0;
            __syncwarp();
            float tj = sm->tbuf[w*16 + j];
            float sj = sm->s[u*PS + j];
            __syncwarp();

            float v2 = sj*sj;
            v2 += __shfl_xor_sync(FULL, v2, 1, 16);
            v2 += __shfl_xor_sync(FULL, v2, 2, 16);
            v2 += __shfl_xor_sync(FULL, v2, 4, 16);
            v2 += __shfl_xor_sync(FULL, v2, 8, 16);
            den_acc += (float)d * v2;

#pragma unroll
            for (int kk = 0; kk < 8; kk++) {
                float su = sm->s[u*PS + kh*8 + kk];
                oa[kk] += su * tj;
                ob[kk] += su * sj;
            }
        }
    }
    __syncthreads();

    // ---- reduce out_adj + ss + den (2 rounds of 8 warps, both at once) ----
    {
        int j = lane & 15, kh = lane >> 4;
        if (lane == 0) sm->red[w] = den_acc;
        for (int round = 0; round < 2; round++) {
            if ((w >> 3) == round) {
#pragma unroll
                for (int kk = 0; kk < 8; kk++) {
                    sm->wk[(w & 7)*256 + (kh*8+kk)*16 + j] = oa[kk];
                    sm->wk[2048 + (w & 7)*256 + (kh*8+kk)*16 + j] = ob[kk];
                }
            }
            __syncthreads();
            if (tid < 256) {
                float v = 0.f, v2 = 0.f;
#pragma unroll
                for (int ww = 0; ww < 8; ww++) {
                    v  += sm->wk[ww*256 + tid];
                    v2 += sm->wk[2048 + ww*256 + tid];
                }
                if (round == 0) { sm->adj[tid] = v; sm->ssm[tid] = v2; }
                else            { sm->adj[tid] += v; sm->ssm[tid] += v2; }
            }
            __syncthreads();
        }
    }

    // ---- losses (CTA partials -> global atomics) ----
    int kq = (tid >> 4) & 15, jq = tid & 15;
    float mincut_part = 0.f;
    if (tid == 0) {
        float den = 0.f;
        for (int i = 0; i < NW; i++) den += sm->red[i];
        float num = 0.f;
        for (int kk = 0; kk < K; kk++) num += sm->adj[kk*K + kk];
        mincut_part = -(num / den);
    }
    float ssv = (tid < 256) ? sm->ssm[tid] : 0.f;
    if (tid < 256) sm->wk[tid] = ssv * ssv;
    __syncthreads();
    for (int off = 128; off > 0; off >>= 1) { if (tid < off) sm->wk[tid] += sm->wk[tid + off]; __syncthreads(); }
    float nrm = sqrtf(sm->wk[0]);
    __syncthreads();
    if (tid < 256) {
        float diff = ssv / nrm - ((kq == jq) ? 0.25f : 0.f);
        sm->wk[tid] = diff * diff;
    }
    __syncthreads();
    for (int off = 128; off > 0; off >>= 1) { if (tid < off) sm->wk[tid] += sm->wk[tid + off]; __syncthreads(); }
    float ortho_part = (tid == 0) ? sqrtf(sm->wk[0]) : 0.f;
    __syncthreads();

    // ---- normalize out_adj ----
    if (tid < 256) {
        float av = (kq == jq) ? 0.f : sm->adj[tid];
        sm->adj[tid] = av;
    }
    __syncthreads();
    if (tid < K) {
        float rs = 0.f;
        for (int jj = 0; jj < K; jj++) rs += sm->adj[tid*K + jj];
        sm->sd[tid] = sqrtf(rs) + EPSF;
    }
    __syncthreads();
    if (tid < 256) sm->adj[tid] = sm->adj[tid] / (sm->sd[kq] * sm->sd[jq]);
    __syncthreads();

    // ---- conv2 on pooled features (one (kc,h) per thread) ----
    {
        int h = tid & 31, kc = tid >> 5;
        float m1 = 0.f;
#pragma unroll
        for (int jj = 0; jj < K; jj++) m1 += sm->adj[kc*K + jj] * sm->px[jj*H + h];
        sm->wk[kc*H + h] = m1;
    }
    __syncthreads();
    {
        int h = tid & 31, kc = tid >> 5;
        float acc = brel2[h];
        for (int c = 0; c < H; c++)
            acc += sm->wk[kc*H + c] * Wrel2[c*H + h] + sm->px[kc*H + c] * Wroot2[c*H + h];
        sm->wk[512 + kc*H + h] = acc;
    }
    __syncthreads();

    // ---- readout + MLP + log_softmax ----
    if (tid < H) {
        float r = 0.f;
#pragma unroll
        for (int kk = 0; kk < K; kk++) r += sm->wk[512 + kk*H + tid];
        sm->sr[tid] = r;
    }
    __syncthreads();
    if (tid < H) {
        float a2 = blin2[tid];
        for (int c = 0; c < H; c++) a2 += sm->sr[c] * Wlin2[c*H + tid];
        sm->sh3[tid] = fmaxf(a2, 0.f);
    }
    __syncthreads();
    if (tid < FOUT) {
        float a3 = blin3[tid];
        for (int c = 0; c < H; c++) a3 += sm->sh3[c] * Wlin3[c*FOUT + tid];
        sm->so[tid] = a3;
    }
    __syncthreads();
    if (tid == 0) {
        float m = sm->so[0];
        for (int i = 1; i < FOUT; i++) m = fmaxf(m, sm->so[i]);
        float s = 0.f;
        for (int i = 0; i < FOUT; i++) s += __expf(sm->so[i] - m);
        float lse = m + __logf(s);
        for (int i = 0; i < FOUT; i++) out[b*FOUT + i] = sm->so[i] - lse;

        // global loss reduction; last CTA writes + resets (graph-replay safe)
        atomicAdd(&g_acc[0], mincut_part * (1.f/(float)B));
        atomicAdd(&g_acc[1], ortho_part  * (1.f/(float)B));
        __threadfence();
        int old = atomicAdd(&g_ctr, 1);
        if (old == B - 1) {
            __threadfence();
            float l0 = g_acc[0], l1 = g_acc[1];
            if (out_size > B*FOUT)     out[B*FOUT]     = l0;
            if (out_size > B*FOUT + 1) out[B*FOUT + 1] = l1;
            g_acc[0] = 0.f; g_acc[1] = 0.f;
            g_ctr = 0;
            __threadfence();
        }
    }
}

// ---------------- launch ----------------
extern "C" void kernel_launch(void* const* d_in, const int* in_sizes, int n_in,
                              void* d_out, int out_size) {
    const float* x     = (const float*)d_in[0];
    const int*   ei    = (const int*)d_in[1];
    const float* Wlin1 = (const float*)d_in[3];
    const float* blin1 = (const float*)d_in[4];
    const float* Wrel1 = (const float*)d_in[5];
    const float* brel1 = (const float*)d_in[6];
    const float* Wroot1= (const float*)d_in[7];
    const float* Wpool = (const float*)d_in[8];
    const float* bpool = (const float*)d_in[9];
    const float* Wrel2 = (const float*)d_in[10];
    const float* brel2 = (const float*)d_in[11];
    const float* Wroot2= (const float*)d_in[12];
    const float* Wlin2 = (const float*)d_in[13];
    const float* blin2 = (const float*)d_in[14];
    const float* Wlin3 = (const float*)d_in[15];
    const float* blin3 = (const float*)d_in[16];
    float* out = (float*)d_out;

    cudaFuncSetAttribute(k_mega, cudaFuncAttributeMaxDynamicSharedMemorySize,
                         (int)sizeof(SMem));

    k_mega<<<B, NTHR, sizeof(SMem)>>>(x, ei, Wlin1, blin1,
                                      Wrel1, brel1, Wroot1, Wpool, bpool,
                                      Wrel2, brel2, Wroot2,
                                      Wlin2, blin2, Wlin3, blin3, out, out_size);
}